// round 10
// baseline (speedup 1.0000x reference)
#include <cuda_runtime.h>
#include <math.h>
#include <stdint.h>

#define BB 8
#define NN 512
#define HH 8
#define DH 64
#define DI 512
#define N3 1536
#define SCALE 0.125f
#define FIXMAX 8.0f

// Scratch (device globals). All tf32-exact fp32 bits.
// k-dims stored with in-block perm8 so mma fragment pairs (k, k+4) are adjacent.
__device__ float g_X[3ull * 4096 * 512];           // [mod][row][perm k]
__device__ float g_WqT[3ull * 1536 * 512];         // [mod][n][perm k]
__device__ float g_WoT[3ull * 512 * 512];          // [mod][n][perm k]
__device__ float g_Q[3ull * BB * HH * NN * DH];    // [mod][b][h][n][perm d], pre-scaled
__device__ float g_K[(size_t)BB * HH * N3 * DH];   // [bh][key][perm d]
__device__ float g_VT[(size_t)BB * HH * DH * N3];  // [bh][d][perm key]
__device__ float g_O[3ull * BB * NN * DI];         // [mod][b][n][perm (h*64+d)]
__device__ int   g_idx[24 * 512];                  // unmasked row indices per (mod,b)
__device__ int   g_cnt[24];
__device__ float g_meanV[64 * 64];                 // [bh][d]
__device__ float g_mvout[24 * 512];                // masked-row output per (mod,b)

__device__ __forceinline__ int perm8(int j) { return ((j & 3) << 1) | (j >> 2); }

__device__ __forceinline__ unsigned f2t(float f) {
    unsigned u;
    asm("cvt.rna.tf32.f32 %0, %1;" : "=r"(u) : "f"(f));
    return u;
}
__device__ __forceinline__ float tf32r(float f) { return __uint_as_float(f2t(f)); }

__device__ __forceinline__ void mma8(float d[4], const unsigned a[4], const unsigned b[2]) {
    asm volatile(
        "mma.sync.aligned.m16n8k8.row.col.f32.tf32.tf32.f32 "
        "{%0,%1,%2,%3}, {%4,%5,%6,%7}, {%8,%9}, {%0,%1,%2,%3};"
        : "+f"(d[0]), "+f"(d[1]), "+f"(d[2]), "+f"(d[3])
        : "r"(a[0]), "r"(a[1]), "r"(a[2]), "r"(a[3]), "r"(b[0]), "r"(b[1]));
}

__device__ __forceinline__ void cpa16(unsigned* dst, const float* src) {
    unsigned d = (unsigned)__cvta_generic_to_shared(dst);
    asm volatile("cp.async.cg.shared.global [%0], [%1], 16;\n" ::"r"(d), "l"(src));
}
#define CP_COMMIT asm volatile("cp.async.commit_group;\n" ::)
#define CP_WAIT1 asm volatile("cp.async.wait_group 1;\n" ::)
#define CP_WAIT0 asm volatile("cp.async.wait_group 0;\n" ::)

// ---------------------------------------------------------------------------
// Prep: X tf32-round + perm8 columns. grid (2048, 3), 256 threads.
// ---------------------------------------------------------------------------
__global__ void prep_x(const float* __restrict__ x0, const float* __restrict__ x1,
                       const float* __restrict__ x2) {
    const int mod = blockIdx.y;
    const float* __restrict__ X = (mod == 0) ? x0 : (mod == 1) ? x1 : x2;
    int i = blockIdx.x * 256 + threadIdx.x;
    int o = i * 4;
    int row = o >> 9, c = o & 511;
    int base = c & ~7;
    float v[4];
#pragma unroll
    for (int q = 0; q < 4; q++) {
        int qq = (c + q) & 7;
        int j = ((qq & 1) << 2) | (qq >> 1);     // inverse perm
        v[q] = tf32r(X[(size_t)row * 512 + base + j]);
    }
    *(float4*)(g_X + (size_t)mod * 4096 * 512 + o) = make_float4(v[0], v[1], v[2], v[3]);
}

// Transpose W [512][N] -> WT [mod][N][512], tf32-rounded, perm8 on k.
__global__ void transpose_w(const float* __restrict__ w0, const float* __restrict__ w1,
                            const float* __restrict__ w2, float* __restrict__ dst,
                            int N) {
    __shared__ float t[32][33];
    const int mod = blockIdx.z;
    const float* __restrict__ W = (mod == 0) ? w0 : (mod == 1) ? w1 : w2;
    float* __restrict__ D = dst + (size_t)mod * N * 512;
    const int n0 = blockIdx.x * 32, k0 = blockIdx.y * 32;
    const int tx = threadIdx.x, ty = threadIdx.y;
#pragma unroll
    for (int j = ty; j < 32; j += 8) t[j][tx] = W[(size_t)(k0 + j) * N + n0 + tx];
    __syncthreads();
#pragma unroll
    for (int j = ty; j < 32; j += 8) {
        int pk = (tx & ~7) | perm8(tx & 7);
        D[(size_t)(n0 + j) * 512 + k0 + pk] = tf32r(t[tx][j]);
    }
}

// ---------------------------------------------------------------------------
// Mask compaction: per (mod,b) list of unmasked row indices + count. grid 24.
// ---------------------------------------------------------------------------
__global__ void compact_mask(const int* __restrict__ m0, const int* __restrict__ m1,
                             const int* __restrict__ m2) {
    const int mb = blockIdx.x;
    const int mod = mb >> 3, b = mb & 7;
    const int* __restrict__ M = (mod == 0) ? m0 : (mod == 1) ? m1 : m2;
    const int tid = threadIdx.x;
    const int on = (M[b * NN + tid] != 0) ? 1 : 0;
    const int lane = tid & 31, w = tid >> 5;
    unsigned ball = __ballot_sync(0xffffffffu, on);
    int pre = __popc(ball & ((1u << lane) - 1u));
    __shared__ int wsum[16];
    if (lane == 31) wsum[w] = pre + on;
    __syncthreads();
    if (tid == 0) {
        int acc = 0;
#pragma unroll
        for (int i = 0; i < 16; i++) { int t = wsum[i]; wsum[i] = acc; acc += t; }
        g_cnt[mb] = acc;
    }
    __syncthreads();
    if (on) g_idx[mb * 512 + wsum[w] + pre] = tid;
}

// ---------------------------------------------------------------------------
// meanV: per bh, mean over 1536 keys of V. grid 64, 128 threads.
// ---------------------------------------------------------------------------
__global__ void mean_v() {
    const int bh = blockIdx.x;
    const int d = threadIdx.x >> 1, half = threadIdx.x & 1;
    const float* row = g_VT + (size_t)bh * DH * N3 + (size_t)d * N3 + half * 768;
    float s = 0.f;
#pragma unroll 4
    for (int i = 0; i < 768; i += 4) {
        float4 v = *(const float4*)(row + i);
        s += v.x + v.y + v.z + v.w;
    }
    s += __shfl_xor_sync(0xffffffffu, s, 1);
    if (!half) g_meanV[bh * 64 + d] = s * (1.0f / 1536.0f);
}

// ---------------------------------------------------------------------------
// mvout: masked-row output = meanV @ Wout, per (mod,b). grid 24, 512 threads.
// ---------------------------------------------------------------------------
__global__ void mvout_gemm() {
    const int mb = blockIdx.x;
    const int mod = mb >> 3, b = mb & 7;
    __shared__ float mv[512];
    const int tid = threadIdx.x;
    {
        int h = tid >> 6, d = tid & 63;
        int pk = (tid & ~7) | perm8(tid & 7);
        mv[pk] = g_meanV[(b * HH + h) * 64 + d];
    }
    __syncthreads();
    const float* w = g_WoT + (size_t)mod * 512 * 512 + (size_t)tid * 512;
    float s = 0.f;
#pragma unroll 4
    for (int k = 0; k < 512; k += 4) {
        float4 wv = *(const float4*)(w + k);
        s += wv.x * mv[k] + wv.y * mv[k + 1] + wv.z * mv[k + 2] + wv.w * mv[k + 3];
    }
    g_mvout[mb * 512 + tid] = s;
}

// ---------------------------------------------------------------------------
// scatter_masked_out: broadcast mvout into masked output rows.
// grid (64, 24), 512 threads; 8 rows per block.
// ---------------------------------------------------------------------------
__global__ void scatter_masked_out(const int* __restrict__ m0, const int* __restrict__ m1,
                                   const int* __restrict__ m2, float* __restrict__ out) {
    const int mb = blockIdx.y;
    const int mod = mb >> 3, b = mb & 7;
    const int* __restrict__ M = (mod == 0) ? m0 : (mod == 1) ? m1 : m2;
    const int tid = threadIdx.x;
    const float v = g_mvout[mb * 512 + tid];
#pragma unroll
    for (int r = 0; r < 8; r++) {
        int n = blockIdx.x * 8 + r;
        if (M[b * NN + n] == 0)
            out[((size_t)mod * 4096 + b * NN + n) * 512 + tid] = v;
    }
}

// ---------------------------------------------------------------------------
// Tensor-core GEMM (QKV): C[4096,1536] = X @ Wq (WT[n][k]). 3-stage cp.async,
// ONE sync per k-chunk. Tile 128x128, 256 thr, k-chunk 32, LDS.64 frags.
// ---------------------------------------------------------------------------
#define SA 40
#define SBT 40
#define XS_W (128 * SA)
#define WS_W (128 * SBT)
#define GEMM_SMEM (3 * (XS_W + WS_W) * 4)

__global__ __launch_bounds__(256) void gemm_qkv(const float* __restrict__ Xbase,
                                                const float* __restrict__ WTbase) {
    extern __shared__ unsigned sh[];
    unsigned* Xs = sh;                  // 3 stages
    unsigned* Ws = sh + 3 * XS_W;

    const int mod = blockIdx.z;
    const float* __restrict__ X = Xbase + (size_t)mod * 4096 * 512;
    const float* __restrict__ WT = WTbase + (size_t)mod * 1536 * 512;

    const int tid = threadIdx.x;
    const int wid = tid >> 5, lane = tid & 31;
    const int grp = lane >> 2, l4 = lane & 3;
    const int wm = wid >> 2, wn = wid & 3;
    const int rowbase = blockIdx.y * 128;
    const int colbase = blockIdx.x * 128;

    float c[4][4][4];
#pragma unroll
    for (int mt = 0; mt < 4; mt++)
#pragma unroll
        for (int nt = 0; nt < 4; nt++)
#pragma unroll
            for (int e = 0; e < 4; e++) c[mt][nt][e] = 0.f;

    const int rr = tid >> 3, cc = (tid & 7) << 2;

    auto ldg_async = [&](int stage, int k0) {
        unsigned* Xst = Xs + stage * XS_W;
        unsigned* Wst = Ws + stage * WS_W;
#pragma unroll
        for (int i = 0; i < 4; i++) {
            cpa16(&Xst[(rr + i * 32) * SA + cc],
                  X + (size_t)(rowbase + rr + i * 32) * 512 + k0 + cc);
            cpa16(&Wst[(rr + i * 32) * SBT + cc],
                  WT + (size_t)(colbase + rr + i * 32) * 512 + k0 + cc);
        }
    };

    ldg_async(0, 0);
    CP_COMMIT;
    ldg_async(1, 32);
    CP_COMMIT;

    int stage = 0, nstage = 2;
    for (int chunk = 0; chunk < 16; chunk++) {
        if (chunk < 15) CP_WAIT1; else CP_WAIT0;
        __syncthreads();
        if (chunk + 2 < 16) {
            ldg_async(nstage, (chunk + 2) * 32);
            CP_COMMIT;
        }

        const unsigned* Xst = Xs + stage * XS_W;
        const unsigned* Wst = Ws + stage * WS_W;
#pragma unroll
        for (int k8 = 0; k8 < 4; k8++) {
            unsigned a[4][4];
#pragma unroll
            for (int mt = 0; mt < 4; mt++) {
                int r0 = wm * 64 + mt * 16 + grp;
                uint2 p0 = *(const uint2*)&Xst[r0 * SA + k8 * 8 + l4 * 2];
                uint2 p1 = *(const uint2*)&Xst[(r0 + 8) * SA + k8 * 8 + l4 * 2];
                a[mt][0] = p0.x; a[mt][2] = p0.y;
                a[mt][1] = p1.x; a[mt][3] = p1.y;
            }
#pragma unroll
            for (int nt = 0; nt < 4; nt++) {
                int col = wn * 32 + nt * 8 + grp;
                uint2 bp = *(const uint2*)&Wst[col * SBT + k8 * 8 + l4 * 2];
                unsigned b[2] = {bp.x, bp.y};
#pragma unroll
                for (int mt = 0; mt < 4; mt++) mma8(c[mt][nt], a[mt], b);
            }
        }
        stage = (stage + 1) % 3;
        nstage = (nstage + 1) % 3;
    }

    // Epilogue: QKV scatter
#pragma unroll
    for (int mt = 0; mt < 4; mt++) {
        int gr0 = rowbase + wm * 64 + mt * 16 + grp;
        int gr1 = gr0 + 8;
#pragma unroll
        for (int nt = 0; nt < 4; nt++) {
            int gc = colbase + wn * 32 + nt * 8 + l4 * 2;
#pragma unroll
            for (int e = 0; e < 4; e++) {
                int gr = (e < 2) ? gr0 : gr1;
                int gcc = gc + (e & 1);
                float v = c[mt][nt][e];
                int b = gr >> 9, n = gr & 511;
                if (gcc < 512) {
                    int h = gcc >> 6, dd = gcc & 63;
                    int pd = (dd & ~7) | perm8(dd & 7);
                    g_Q[((((size_t)mod * BB + b) * HH + h) * NN + n) * DH + pd] =
                        tf32r(v * SCALE);
                } else if (gcc < 1024) {
                    int c2 = gcc - 512, h = c2 >> 6, dd = c2 & 63;
                    int pd = (dd & ~7) | perm8(dd & 7);
                    g_K[(((size_t)b * HH + h) * N3 + mod * NN + n) * DH + pd] = tf32r(v);
                } else {
                    int c2 = gcc - 1024, h = c2 >> 6, dd = c2 & 63;
                    int key = mod * NN + n;
                    int pk = (key & ~7) | perm8(key & 7);
                    g_VT[(((size_t)b * HH + h) * DH + dd) * N3 + pk] = tf32r(v);
                }
            }
        }
    }
}

// ---------------------------------------------------------------------------
// Out GEMM over COMPACTED rows: out[rows] = g_O[gathered] @ Wout (WT form).
// grid (4 coltiles, 4 rowtiles, 24 mb), 256 thr, 3-stage, early-exit.
// ---------------------------------------------------------------------------
__global__ __launch_bounds__(256) void gemm_out(const float* __restrict__ WTbase,
                                                float* __restrict__ out) {
    extern __shared__ unsigned sh[];
    unsigned* Xs = sh;
    unsigned* Ws = sh + 3 * XS_W;

    const int mb = blockIdx.z;
    const int mod = mb >> 3, b = mb & 7;
    const int cnt = g_cnt[mb];
    const int rowbase = blockIdx.y * 128;
    if (rowbase >= cnt) return;
    const int colbase = blockIdx.x * 128;
    const int gmax = cnt - 1;
    const int* idxp = g_idx + mb * 512;

    const float* __restrict__ Xg = g_O + (size_t)mb * NN * DI;
    const float* __restrict__ WT = WTbase + (size_t)mod * 512 * 512;

    const int tid = threadIdx.x;
    const int wid = tid >> 5, lane = tid & 31;
    const int grp = lane >> 2, l4 = lane & 3;
    const int wm = wid >> 2, wn = wid & 3;

    float c[4][4][4];
#pragma unroll
    for (int mt = 0; mt < 4; mt++)
#pragma unroll
        for (int nt = 0; nt < 4; nt++)
#pragma unroll
            for (int e = 0; e < 4; e++) c[mt][nt][e] = 0.f;

    const int rr = tid >> 3, cc = (tid & 7) << 2;

    // Gathered A-row pointers (constant across chunks)
    const float* arow[4];
#pragma unroll
    for (int i = 0; i < 4; i++)
        arow[i] = Xg + (size_t)idxp[min(rowbase + rr + i * 32, gmax)] * DI;

    auto ldg_async = [&](int stage, int k0) {
        unsigned* Xst = Xs + stage * XS_W;
        unsigned* Wst = Ws + stage * WS_W;
#pragma unroll
        for (int i = 0; i < 4; i++) {
            cpa16(&Xst[(rr + i * 32) * SA + cc], arow[i] + k0 + cc);
            cpa16(&Wst[(rr + i * 32) * SBT + cc],
                  WT + (size_t)(colbase + rr + i * 32) * 512 + k0 + cc);
        }
    };

    ldg_async(0, 0);
    CP_COMMIT;
    ldg_async(1, 32);
    CP_COMMIT;

    int stage = 0, nstage = 2;
    for (int chunk = 0; chunk < 16; chunk++) {
        if (chunk < 15) CP_WAIT1; else CP_WAIT0;
        __syncthreads();
        if (chunk + 2 < 16) {
            ldg_async(nstage, (chunk + 2) * 32);
            CP_COMMIT;
        }

        const unsigned* Xst = Xs + stage * XS_W;
        const unsigned* Wst = Ws + stage * WS_W;
#pragma unroll
        for (int k8 = 0; k8 < 4; k8++) {
            unsigned a[4][4];
#pragma unroll
            for (int mt = 0; mt < 4; mt++) {
                int r0 = wm * 64 + mt * 16 + grp;
                uint2 p0 = *(const uint2*)&Xst[r0 * SA + k8 * 8 + l4 * 2];
                uint2 p1 = *(const uint2*)&Xst[(r0 + 8) * SA + k8 * 8 + l4 * 2];
                a[mt][0] = p0.x; a[mt][2] = p0.y;
                a[mt][1] = p1.x; a[mt][3] = p1.y;
            }
#pragma unroll
            for (int nt = 0; nt < 4; nt++) {
                int col = wn * 32 + nt * 8 + grp;
                uint2 bp = *(const uint2*)&Wst[col * SBT + k8 * 8 + l4 * 2];
                unsigned bb[2] = {bp.x, bp.y};
#pragma unroll
                for (int mt = 0; mt < 4; mt++) mma8(c[mt][nt], a[mt], bb);
            }
        }
        stage = (stage + 1) % 3;
        nstage = (nstage + 1) % 3;
    }

    // Epilogue: scatter to original output rows (guarded)
#pragma unroll
    for (int mt = 0; mt < 4; mt++) {
        int gr0 = rowbase + wm * 64 + mt * 16 + grp;   // compacted indices
        int gr1 = gr0 + 8;
#pragma unroll
        for (int nt = 0; nt < 4; nt++) {
            int gc = colbase + wn * 32 + nt * 8 + l4 * 2;
            if (gr0 < cnt) {
                size_t orow = (size_t)mod * 4096 + b * NN + idxp[gr0];
                *(float2*)(out + orow * 512 + gc) = make_float2(c[mt][nt][0], c[mt][nt][1]);
            }
            if (gr1 < cnt) {
                size_t orow = (size_t)mod * 4096 + b * NN + idxp[gr1];
                *(float2*)(out + orow * 512 + gc) = make_float2(c[mt][nt][2], c[mt][nt][3]);
            }
        }
    }
}

// ---------------------------------------------------------------------------
// Flash attention over compacted rows, FIXED-MAX softmax (no online max).
// grid (8 qtiles of 64, 64 bh, 3 mod), 128 thr; early exit past cnt.
// ---------------------------------------------------------------------------
#define SK 72
#define SV 72
#define KS_W (64 * SK)
#define VS_W (64 * SV)
#define ATT_SMEM ((2 * KS_W + 2 * VS_W) * 4)

__global__ __launch_bounds__(128, 3) void attn_tc() {
    extern __shared__ unsigned sh[];
    unsigned* Ks = sh;
    unsigned* Vs = sh + 2 * KS_W;

    const int mod = blockIdx.z;
    const int bh = blockIdx.y;
    const int b = bh >> 3, h = bh & 7;
    const int qt = blockIdx.x;
    const int mb = mod * 8 + b;

    const int cnt = g_cnt[mb];
    if (qt * 64 >= cnt) return;

    const int tid = threadIdx.x;
    const int wid = tid >> 5, lane = tid & 31;
    const int grp = lane >> 2, l4 = lane & 3;

    const int r0 = wid * 16 + grp;
    const int r1 = r0 + 8;
    const int gr0 = qt * 64 + r0, gr1 = qt * 64 + r1;
    const int gmax = cnt - 1;
    const int* idxp = g_idx + mb * 512;
    const int i0 = idxp[min(gr0, gmax)];
    const int i1 = idxp[min(gr1, gmax)];

    const float* Qg = g_Q + (((size_t)mb * HH + h) * NN) * DH;
    unsigned qa[8][4];
#pragma unroll
    for (int k8 = 0; k8 < 8; k8++) {
        float2 p0 = *(const float2*)(Qg + (size_t)i0 * 64 + k8 * 8 + l4 * 2);
        float2 p1 = *(const float2*)(Qg + (size_t)i1 * 64 + k8 * 8 + l4 * 2);
        qa[k8][0] = __float_as_uint(p0.x);
        qa[k8][2] = __float_as_uint(p0.y);
        qa[k8][1] = __float_as_uint(p1.x);
        qa[k8][3] = __float_as_uint(p1.y);
    }

    float l_0 = 0.f, l_1 = 0.f;
    float o[8][4];
#pragma unroll
    for (int nt = 0; nt < 8; nt++)
#pragma unroll
        for (int e = 0; e < 4; e++) o[nt][e] = 0.f;

    const float* Kg = g_K + (size_t)bh * N3 * DH;
    const float* VTg = g_VT + (size_t)bh * DH * N3;

    auto ldkv_async = [&](int stage, int kt) {
        unsigned* Kst = Ks + stage * KS_W;
        unsigned* Vst = Vs + stage * VS_W;
#pragma unroll
        for (int i = 0; i < 8; i++) {
            int v = tid + i * 128;
            int r = v >> 4, c4 = (v & 15) << 2;
            cpa16(&Kst[r * SK + c4], Kg + (size_t)(kt * 64 + r) * 64 + c4);
            cpa16(&Vst[r * SV + c4], VTg + (size_t)r * N3 + kt * 64 + c4);
        }
    };

    ldkv_async(0, 0);
    CP_COMMIT;

    for (int kt = 0; kt < 24; kt++) {
        if (kt < 23) {
            ldkv_async((kt + 1) & 1, kt + 1);
            CP_COMMIT;
            CP_WAIT1;
        } else {
            CP_WAIT0;
        }
        __syncthreads();

        const unsigned* Kst = Ks + (kt & 1) * KS_W;
        const unsigned* Vst = Vs + (kt & 1) * VS_W;

        // S = Q K^T
        float s[8][4];
#pragma unroll
        for (int nt = 0; nt < 8; nt++)
#pragma unroll
            for (int e = 0; e < 4; e++) s[nt][e] = 0.f;
#pragma unroll
        for (int k8 = 0; k8 < 8; k8++) {
#pragma unroll
            for (int nt = 0; nt < 8; nt++) {
                int key = nt * 8 + grp;
                uint2 bp = *(const uint2*)&Kst[key * SK + k8 * 8 + l4 * 2];
                unsigned bf[2] = {bp.x, bp.y};
                mma8(s[nt], qa[k8], bf);
            }
        }

        // Fixed-max softmax: P = exp(S - FIXMAX), no rescaling of O ever.
        float sum0 = 0.f, sum1 = 0.f;
#pragma unroll
        for (int nt = 0; nt < 8; nt++) {
            s[nt][0] = __expf(s[nt][0] - FIXMAX);
            s[nt][1] = __expf(s[nt][1] - FIXMAX);
            s[nt][2] = __expf(s[nt][2] - FIXMAX);
            s[nt][3] = __expf(s[nt][3] - FIXMAX);
            sum0 += s[nt][0] + s[nt][1];
            sum1 += s[nt][2] + s[nt][3];
        }
        sum0 += __shfl_xor_sync(0xffffffffu, sum0, 1);
        sum0 += __shfl_xor_sync(0xffffffffu, sum0, 2);
        sum1 += __shfl_xor_sync(0xffffffffu, sum1, 1);
        sum1 += __shfl_xor_sync(0xffffffffu, sum1, 2);
        l_0 += sum0;
        l_1 += sum1;

        // O += P @ V  (C-frag -> A-frag via quad shuffles; V^T frags LDS.64)
        const int src = (grp << 2) | (l4 >> 1);
        const bool odd = (l4 & 1);
#pragma unroll
        for (int k8 = 0; k8 < 8; k8++) {
            float t0 = __shfl_sync(0xffffffffu, s[k8][0], src);
            float t1 = __shfl_sync(0xffffffffu, s[k8][1], src);
            float t2 = __shfl_sync(0xffffffffu, s[k8][2], src);
            float t3 = __shfl_sync(0xffffffffu, s[k8][3], src);
            float u0 = __shfl_sync(0xffffffffu, s[k8][0], src + 2);
            float u1 = __shfl_sync(0xffffffffu, s[k8][1], src + 2);
            float u2 = __shfl_sync(0xffffffffu, s[k8][2], src + 2);
            float u3 = __shfl_sync(0xffffffffu, s[k8][3], src + 2);
            unsigned pa[4];
            pa[0] = f2t(odd ? t1 : t0);
            pa[1] = f2t(odd ? t3 : t2);
            pa[2] = f2t(odd ? u1 : u0);
            pa[3] = f2t(odd ? u3 : u2);
#pragma unroll
            for (int nt = 0; nt < 8; nt++) {
                int drow = nt * 8 + grp;
                uint2 bp = *(const uint2*)&Vst[drow * SV + k8 * 8 + l4 * 2];
                unsigned bf[2] = {bp.x, bp.y};
                mma8(o[nt], pa, bf);
            }
        }
        __syncthreads();
    }

    // Epilogue: normalize, tf32-round, scatter to original rows (perm-d cols)
    float linv0 = 1.f / l_0, linv1 = 1.f / l_1;
    size_t base0 = ((size_t)mb * NN + i0) * DI + h * 64;
    size_t base1 = ((size_t)mb * NN + i1) * DI + h * 64;
    const int pd0 = perm8(2 * l4);
    const int pd1 = perm8(2 * l4 + 1);
    if (gr0 < cnt) {
#pragma unroll
        for (int nt = 0; nt < 8; nt++) {
            g_O[base0 + nt * 8 + pd0] = tf32r(o[nt][0] * linv0);
            g_O[base0 + nt * 8 + pd1] = tf32r(o[nt][1] * linv0);
        }
    }
    if (gr1 < cnt) {
#pragma unroll
        for (int nt = 0; nt < 8; nt++) {
            g_O[base1 + nt * 8 + pd0] = tf32r(o[nt][2] * linv1);
            g_O[base1 + nt * 8 + pd1] = tf32r(o[nt][3] * linv1);
        }
    }
}

// ---------------------------------------------------------------------------
// Input order: 0:x0 1:m0 2:Wqkv0 3:Wout0 | 4:x1 5:m1 6:Wqkv1 7:Wout1 | 8:...
// ---------------------------------------------------------------------------
extern "C" void kernel_launch(void* const* d_in, const int* in_sizes, int n_in,
                              void* d_out, int out_size) {
    const float* x0  = (const float*)d_in[0];
    const int*   m0  = (const int*)d_in[1];
    const float* wq0 = (const float*)d_in[2];
    const float* wo0 = (const float*)d_in[3];
    const float* x1  = (const float*)d_in[4];
    const int*   m1  = (const int*)d_in[5];
    const float* wq1 = (const float*)d_in[6];
    const float* wo1 = (const float*)d_in[7];
    const float* x2  = (const float*)d_in[8];
    const int*   m2  = (const int*)d_in[9];
    const float* wq2 = (const float*)d_in[10];
    const float* wo2 = (const float*)d_in[11];
    float* out = (float*)d_out;

    static int configured = 0;
    if (!configured) {
        cudaFuncSetAttribute(gemm_qkv,
                             cudaFuncAttributeMaxDynamicSharedMemorySize, GEMM_SMEM);
        cudaFuncSetAttribute(gemm_out,
                             cudaFuncAttributeMaxDynamicSharedMemorySize, GEMM_SMEM);
        cudaFuncSetAttribute(attn_tc,
                             cudaFuncAttributeMaxDynamicSharedMemorySize, ATT_SMEM);
        configured = 1;
    }

    float *gx, *gwqt, *gwot;
    cudaGetSymbolAddress((void**)&gx, g_X);
    cudaGetSymbolAddress((void**)&gwqt, g_WqT);
    cudaGetSymbolAddress((void**)&gwot, g_WoT);

    prep_x<<<dim3(2048, 3), 256>>>(x0, x1, x2);
    transpose_w<<<dim3(48, 16, 3), dim3(32, 8)>>>(wq0, wq1, wq2, gwqt, 1536);
    transpose_w<<<dim3(16, 16, 3), dim3(32, 8)>>>(wo0, wo1, wo2, gwot, 512);
    compact_mask<<<24, 512>>>(m0, m1, m2);
    gemm_qkv<<<dim3(12, 32, 3), 256, GEMM_SMEM>>>(gx, gwqt);
    mean_v<<<64, 128>>>();
    mvout_gemm<<<24, 512>>>();
    scatter_masked_out<<<dim3(64, 24), 512>>>(m0, m1, m2, out);
    attn_tc<<<dim3(8, 64, 3), 128, ATT_SMEM>>>();
    gemm_out<<<dim3(4, 4, 24), 256, GEMM_SMEM>>>(gwot, out);
}

// round 11
// speedup vs baseline: 1.1226x; 1.1226x over previous
#include <cuda_runtime.h>
#include <math.h>
#include <stdint.h>

#define BB 8
#define NN 512
#define HH 8
#define DH 64
#define DI 512
#define N3 1536
#define SCALE 0.125f
#define FIXMAX 8.0f

// Scratch (device globals). All tf32-exact fp32 bits.
// k-dims stored with in-block perm8 so mma fragment pairs (k, k+4) are adjacent.
__device__ float g_X[3ull * 4096 * 512];           // [mod][row][perm k]
__device__ float g_WqT[3ull * 1536 * 512];         // [mod][n][perm k]
__device__ float g_WoT[3ull * 512 * 512];          // [mod][n][perm k]
__device__ float g_Q[3ull * BB * HH * NN * DH];    // [mod][b][h][n][perm d], pre-scaled
__device__ float g_K[(size_t)BB * HH * N3 * DH];   // [bh][key][perm d]
__device__ float g_VT[(size_t)BB * HH * DH * N3];  // [bh][d][perm key]
__device__ float g_O[3ull * BB * NN * DI];         // [mod][b][n][perm (h*64+d)]
__device__ int   g_idx[24 * 512];                  // unmasked row indices per (mod,b)
__device__ int   g_cnt[24];
__device__ float g_meanV[64 * 64];                 // [bh][d]
__device__ float g_mvout[24 * 512];                // masked-row output per (mod,b)

__device__ __forceinline__ int perm8(int j) { return ((j & 3) << 1) | (j >> 2); }

__device__ __forceinline__ unsigned f2t(float f) {
    unsigned u;
    asm("cvt.rna.tf32.f32 %0, %1;" : "=r"(u) : "f"(f));
    return u;
}
__device__ __forceinline__ float tf32r(float f) { return __uint_as_float(f2t(f)); }

__device__ __forceinline__ void mma8(float d[4], const unsigned a[4], const unsigned b[2]) {
    asm volatile(
        "mma.sync.aligned.m16n8k8.row.col.f32.tf32.tf32.f32 "
        "{%0,%1,%2,%3}, {%4,%5,%6,%7}, {%8,%9}, {%0,%1,%2,%3};"
        : "+f"(d[0]), "+f"(d[1]), "+f"(d[2]), "+f"(d[3])
        : "r"(a[0]), "r"(a[1]), "r"(a[2]), "r"(a[3]), "r"(b[0]), "r"(b[1]));
}

__device__ __forceinline__ void cpa16(unsigned* dst, const float* src) {
    unsigned d = (unsigned)__cvta_generic_to_shared(dst);
    asm volatile("cp.async.cg.shared.global [%0], [%1], 16;\n" ::"r"(d), "l"(src));
}
#define CP_COMMIT asm volatile("cp.async.commit_group;\n" ::)
#define CP_WAIT1 asm volatile("cp.async.wait_group 1;\n" ::)
#define CP_WAIT0 asm volatile("cp.async.wait_group 0;\n" ::)

// ---------------------------------------------------------------------------
// Prep: X tf32-round + perm8 columns. grid (2048, 3), 256 threads.
// ---------------------------------------------------------------------------
__global__ void prep_x(const float* __restrict__ x0, const float* __restrict__ x1,
                       const float* __restrict__ x2) {
    const int mod = blockIdx.y;
    const float* __restrict__ X = (mod == 0) ? x0 : (mod == 1) ? x1 : x2;
    int i = blockIdx.x * 256 + threadIdx.x;
    int o = i * 4;
    int row = o >> 9, c = o & 511;
    int base = c & ~7;
    float v[4];
#pragma unroll
    for (int q = 0; q < 4; q++) {
        int qq = (c + q) & 7;
        int j = ((qq & 1) << 2) | (qq >> 1);     // inverse perm
        v[q] = tf32r(X[(size_t)row * 512 + base + j]);
    }
    *(float4*)(g_X + (size_t)mod * 4096 * 512 + o) = make_float4(v[0], v[1], v[2], v[3]);
}

// Transpose W [512][N] -> WT [mod][N][512], tf32-rounded, perm8 on k.
__global__ void transpose_w(const float* __restrict__ w0, const float* __restrict__ w1,
                            const float* __restrict__ w2, float* __restrict__ dst,
                            int N) {
    __shared__ float t[32][33];
    const int mod = blockIdx.z;
    const float* __restrict__ W = (mod == 0) ? w0 : (mod == 1) ? w1 : w2;
    float* __restrict__ D = dst + (size_t)mod * N * 512;
    const int n0 = blockIdx.x * 32, k0 = blockIdx.y * 32;
    const int tx = threadIdx.x, ty = threadIdx.y;
#pragma unroll
    for (int j = ty; j < 32; j += 8) t[j][tx] = W[(size_t)(k0 + j) * N + n0 + tx];
    __syncthreads();
#pragma unroll
    for (int j = ty; j < 32; j += 8) {
        int pk = (tx & ~7) | perm8(tx & 7);
        D[(size_t)(n0 + j) * 512 + k0 + pk] = tf32r(t[tx][j]);
    }
}

// ---------------------------------------------------------------------------
// Mask compaction: per (mod,b) list of unmasked row indices + count. grid 24.
// ---------------------------------------------------------------------------
__global__ void compact_mask(const int* __restrict__ m0, const int* __restrict__ m1,
                             const int* __restrict__ m2) {
    const int mb = blockIdx.x;
    const int mod = mb >> 3, b = mb & 7;
    const int* __restrict__ M = (mod == 0) ? m0 : (mod == 1) ? m1 : m2;
    const int tid = threadIdx.x;
    const int on = (M[b * NN + tid] != 0) ? 1 : 0;
    const int lane = tid & 31, w = tid >> 5;
    unsigned ball = __ballot_sync(0xffffffffu, on);
    int pre = __popc(ball & ((1u << lane) - 1u));
    __shared__ int wsum[16];
    if (lane == 31) wsum[w] = pre + on;
    __syncthreads();
    if (tid == 0) {
        int acc = 0;
#pragma unroll
        for (int i = 0; i < 16; i++) { int t = wsum[i]; wsum[i] = acc; acc += t; }
        g_cnt[mb] = acc;
    }
    __syncthreads();
    if (on) g_idx[mb * 512 + wsum[w] + pre] = tid;
}

// ---------------------------------------------------------------------------
// meanV: per bh, mean over 1536 keys of V. grid 64, 128 threads.
// ---------------------------------------------------------------------------
__global__ void mean_v() {
    const int bh = blockIdx.x;
    const int d = threadIdx.x >> 1, half = threadIdx.x & 1;
    const float* row = g_VT + (size_t)bh * DH * N3 + (size_t)d * N3 + half * 768;
    float s = 0.f;
#pragma unroll 4
    for (int i = 0; i < 768; i += 4) {
        float4 v = *(const float4*)(row + i);
        s += v.x + v.y + v.z + v.w;
    }
    s += __shfl_xor_sync(0xffffffffu, s, 1);
    if (!half) g_meanV[bh * 64 + d] = s * (1.0f / 1536.0f);
}

// ---------------------------------------------------------------------------
// mvout: masked-row output = meanV @ Wout, per (mod,b). grid 24, 512 threads.
// ---------------------------------------------------------------------------
__global__ void mvout_gemm() {
    const int mb = blockIdx.x;
    const int mod = mb >> 3, b = mb & 7;
    __shared__ float mv[512];
    const int tid = threadIdx.x;
    {
        int h = tid >> 6, d = tid & 63;
        int pk = (tid & ~7) | perm8(tid & 7);
        mv[pk] = g_meanV[(b * HH + h) * 64 + d];
    }
    __syncthreads();
    const float* w = g_WoT + (size_t)mod * 512 * 512 + (size_t)tid * 512;
    float s = 0.f;
#pragma unroll 4
    for (int k = 0; k < 512; k += 4) {
        float4 wv = *(const float4*)(w + k);
        s += wv.x * mv[k] + wv.y * mv[k + 1] + wv.z * mv[k + 2] + wv.w * mv[k + 3];
    }
    g_mvout[mb * 512 + tid] = s;
}

// ---------------------------------------------------------------------------
// scatter_masked_out: broadcast mvout into masked output rows.
// grid (64, 24), 512 threads; 8 rows per block.
// ---------------------------------------------------------------------------
__global__ void scatter_masked_out(const int* __restrict__ m0, const int* __restrict__ m1,
                                   const int* __restrict__ m2, float* __restrict__ out) {
    const int mb = blockIdx.y;
    const int mod = mb >> 3, b = mb & 7;
    const int* __restrict__ M = (mod == 0) ? m0 : (mod == 1) ? m1 : m2;
    const int tid = threadIdx.x;
    const float v = g_mvout[mb * 512 + tid];
#pragma unroll
    for (int r = 0; r < 8; r++) {
        int n = blockIdx.x * 8 + r;
        if (M[b * NN + n] == 0)
            out[((size_t)mod * 4096 + b * NN + n) * 512 + tid] = v;
    }
}

// ---------------------------------------------------------------------------
// Tensor-core GEMM (QKV): 2-stage cp.async (80KB smem -> 2 CTAs/SM).
// Tile 128x128, 256 thr, k-chunk 32, LDS.64 fragments both operands.
// ---------------------------------------------------------------------------
#define SA 40
#define SBT 40
#define XS_W (128 * SA)
#define WS_W (128 * SBT)
#define GEMM_SMEM (2 * (XS_W + WS_W) * 4)

__global__ __launch_bounds__(256) void gemm_qkv(const float* __restrict__ Xbase,
                                                const float* __restrict__ WTbase) {
    extern __shared__ unsigned sh[];
    unsigned* Xs = sh;                  // 2 stages
    unsigned* Ws = sh + 2 * XS_W;

    const int mod = blockIdx.z;
    const float* __restrict__ X = Xbase + (size_t)mod * 4096 * 512;
    const float* __restrict__ WT = WTbase + (size_t)mod * 1536 * 512;

    const int tid = threadIdx.x;
    const int wid = tid >> 5, lane = tid & 31;
    const int grp = lane >> 2, l4 = lane & 3;
    const int wm = wid >> 2, wn = wid & 3;
    const int rowbase = blockIdx.y * 128;
    const int colbase = blockIdx.x * 128;

    float c[4][4][4];
#pragma unroll
    for (int mt = 0; mt < 4; mt++)
#pragma unroll
        for (int nt = 0; nt < 4; nt++)
#pragma unroll
            for (int e = 0; e < 4; e++) c[mt][nt][e] = 0.f;

    const int rr = tid >> 3, cc = (tid & 7) << 2;

    auto ldg_async = [&](int stage, int k0) {
        unsigned* Xst = Xs + stage * XS_W;
        unsigned* Wst = Ws + stage * WS_W;
#pragma unroll
        for (int i = 0; i < 4; i++) {
            cpa16(&Xst[(rr + i * 32) * SA + cc],
                  X + (size_t)(rowbase + rr + i * 32) * 512 + k0 + cc);
            cpa16(&Wst[(rr + i * 32) * SBT + cc],
                  WT + (size_t)(colbase + rr + i * 32) * 512 + k0 + cc);
        }
    };

    ldg_async(0, 0);
    CP_COMMIT;

    for (int chunk = 0; chunk < 16; chunk++) {
        if (chunk < 15) {
            ldg_async((chunk + 1) & 1, (chunk + 1) * 32);
            CP_COMMIT;
            CP_WAIT1;
        } else {
            CP_WAIT0;
        }
        __syncthreads();

        const unsigned* Xst = Xs + (chunk & 1) * XS_W;
        const unsigned* Wst = Ws + (chunk & 1) * WS_W;
#pragma unroll
        for (int k8 = 0; k8 < 4; k8++) {
            unsigned a[4][4];
#pragma unroll
            for (int mt = 0; mt < 4; mt++) {
                int r0 = wm * 64 + mt * 16 + grp;
                uint2 p0 = *(const uint2*)&Xst[r0 * SA + k8 * 8 + l4 * 2];
                uint2 p1 = *(const uint2*)&Xst[(r0 + 8) * SA + k8 * 8 + l4 * 2];
                a[mt][0] = p0.x; a[mt][2] = p0.y;
                a[mt][1] = p1.x; a[mt][3] = p1.y;
            }
#pragma unroll
            for (int nt = 0; nt < 4; nt++) {
                int col = wn * 32 + nt * 8 + grp;
                uint2 bp = *(const uint2*)&Wst[col * SBT + k8 * 8 + l4 * 2];
                unsigned b[2] = {bp.x, bp.y};
#pragma unroll
                for (int mt = 0; mt < 4; mt++) mma8(c[mt][nt], a[mt], b);
            }
        }
        __syncthreads();
    }

    // Epilogue: QKV scatter
#pragma unroll
    for (int mt = 0; mt < 4; mt++) {
        int gr0 = rowbase + wm * 64 + mt * 16 + grp;
        int gr1 = gr0 + 8;
#pragma unroll
        for (int nt = 0; nt < 4; nt++) {
            int gc = colbase + wn * 32 + nt * 8 + l4 * 2;
#pragma unroll
            for (int e = 0; e < 4; e++) {
                int gr = (e < 2) ? gr0 : gr1;
                int gcc = gc + (e & 1);
                float v = c[mt][nt][e];
                int b = gr >> 9, n = gr & 511;
                if (gcc < 512) {
                    int h = gcc >> 6, dd = gcc & 63;
                    int pd = (dd & ~7) | perm8(dd & 7);
                    g_Q[((((size_t)mod * BB + b) * HH + h) * NN + n) * DH + pd] =
                        tf32r(v * SCALE);
                } else if (gcc < 1024) {
                    int c2 = gcc - 512, h = c2 >> 6, dd = c2 & 63;
                    int pd = (dd & ~7) | perm8(dd & 7);
                    g_K[(((size_t)b * HH + h) * N3 + mod * NN + n) * DH + pd] = tf32r(v);
                } else {
                    int c2 = gcc - 1024, h = c2 >> 6, dd = c2 & 63;
                    int key = mod * NN + n;
                    int pk = (key & ~7) | perm8(key & 7);
                    g_VT[(((size_t)b * HH + h) * DH + dd) * N3 + pk] = tf32r(v);
                }
            }
        }
    }
}

// ---------------------------------------------------------------------------
// Out GEMM over COMPACTED rows: out[rows] = g_O[gathered] @ Wout (WT form).
// grid (4 coltiles, 4 rowtiles, 24 mb), 256 thr, 2-stage, early-exit.
// ---------------------------------------------------------------------------
__global__ __launch_bounds__(256) void gemm_out(const float* __restrict__ WTbase,
                                                float* __restrict__ out) {
    extern __shared__ unsigned sh[];
    unsigned* Xs = sh;
    unsigned* Ws = sh + 2 * XS_W;

    const int mb = blockIdx.z;
    const int mod = mb >> 3, b = mb & 7;
    const int cnt = g_cnt[mb];
    const int rowbase = blockIdx.y * 128;
    if (rowbase >= cnt) return;
    const int colbase = blockIdx.x * 128;
    const int gmax = cnt - 1;
    const int* idxp = g_idx + mb * 512;

    const float* __restrict__ Xg = g_O + (size_t)mb * NN * DI;
    const float* __restrict__ WT = WTbase + (size_t)mod * 512 * 512;

    const int tid = threadIdx.x;
    const int wid = tid >> 5, lane = tid & 31;
    const int grp = lane >> 2, l4 = lane & 3;
    const int wm = wid >> 2, wn = wid & 3;

    float c[4][4][4];
#pragma unroll
    for (int mt = 0; mt < 4; mt++)
#pragma unroll
        for (int nt = 0; nt < 4; nt++)
#pragma unroll
            for (int e = 0; e < 4; e++) c[mt][nt][e] = 0.f;

    const int rr = tid >> 3, cc = (tid & 7) << 2;

    const float* arow[4];
#pragma unroll
    for (int i = 0; i < 4; i++)
        arow[i] = Xg + (size_t)idxp[min(rowbase + rr + i * 32, gmax)] * DI;

    auto ldg_async = [&](int stage, int k0) {
        unsigned* Xst = Xs + stage * XS_W;
        unsigned* Wst = Ws + stage * WS_W;
#pragma unroll
        for (int i = 0; i < 4; i++) {
            cpa16(&Xst[(rr + i * 32) * SA + cc], arow[i] + k0 + cc);
            cpa16(&Wst[(rr + i * 32) * SBT + cc],
                  WT + (size_t)(colbase + rr + i * 32) * 512 + k0 + cc);
        }
    };

    ldg_async(0, 0);
    CP_COMMIT;

    for (int chunk = 0; chunk < 16; chunk++) {
        if (chunk < 15) {
            ldg_async((chunk + 1) & 1, (chunk + 1) * 32);
            CP_COMMIT;
            CP_WAIT1;
        } else {
            CP_WAIT0;
        }
        __syncthreads();

        const unsigned* Xst = Xs + (chunk & 1) * XS_W;
        const unsigned* Wst = Ws + (chunk & 1) * WS_W;
#pragma unroll
        for (int k8 = 0; k8 < 4; k8++) {
            unsigned a[4][4];
#pragma unroll
            for (int mt = 0; mt < 4; mt++) {
                int r0 = wm * 64 + mt * 16 + grp;
                uint2 p0 = *(const uint2*)&Xst[r0 * SA + k8 * 8 + l4 * 2];
                uint2 p1 = *(const uint2*)&Xst[(r0 + 8) * SA + k8 * 8 + l4 * 2];
                a[mt][0] = p0.x; a[mt][2] = p0.y;
                a[mt][1] = p1.x; a[mt][3] = p1.y;
            }
#pragma unroll
            for (int nt = 0; nt < 4; nt++) {
                int col = wn * 32 + nt * 8 + grp;
                uint2 bp = *(const uint2*)&Wst[col * SBT + k8 * 8 + l4 * 2];
                unsigned bb[2] = {bp.x, bp.y};
#pragma unroll
                for (int mt = 0; mt < 4; mt++) mma8(c[mt][nt], a[mt], bb);
            }
        }
        __syncthreads();
    }

    // Epilogue: scatter to original output rows (guarded)
#pragma unroll
    for (int mt = 0; mt < 4; mt++) {
        int gr0 = rowbase + wm * 64 + mt * 16 + grp;   // compacted indices
        int gr1 = gr0 + 8;
#pragma unroll
        for (int nt = 0; nt < 4; nt++) {
            int gc = colbase + wn * 32 + nt * 8 + l4 * 2;
            if (gr0 < cnt) {
                size_t orow = (size_t)mod * 4096 + b * NN + idxp[gr0];
                *(float2*)(out + orow * 512 + gc) = make_float2(c[mt][nt][0], c[mt][nt][1]);
            }
            if (gr1 < cnt) {
                size_t orow = (size_t)mod * 4096 + b * NN + idxp[gr1];
                *(float2*)(out + orow * 512 + gc) = make_float2(c[mt][nt][2], c[mt][nt][3]);
            }
        }
    }
}

// ---------------------------------------------------------------------------
// Flash attention over compacted rows, FIXED-MAX softmax (no online max).
// grid (8 qtiles of 64, 64 bh, 3 mod), 128 thr; early exit past cnt.
// ---------------------------------------------------------------------------
#define SK 72
#define SV 72
#define KS_W (64 * SK)
#define VS_W (64 * SV)
#define ATT_SMEM ((2 * KS_W + 2 * VS_W) * 4)

__global__ __launch_bounds__(128, 3) void attn_tc() {
    extern __shared__ unsigned sh[];
    unsigned* Ks = sh;
    unsigned* Vs = sh + 2 * KS_W;

    const int mod = blockIdx.z;
    const int bh = blockIdx.y;
    const int b = bh >> 3, h = bh & 7;
    const int qt = blockIdx.x;
    const int mb = mod * 8 + b;

    const int cnt = g_cnt[mb];
    if (qt * 64 >= cnt) return;

    const int tid = threadIdx.x;
    const int wid = tid >> 5, lane = tid & 31;
    const int grp = lane >> 2, l4 = lane & 3;

    const int r0 = wid * 16 + grp;
    const int r1 = r0 + 8;
    const int gr0 = qt * 64 + r0, gr1 = qt * 64 + r1;
    const int gmax = cnt - 1;
    const int* idxp = g_idx + mb * 512;
    const int i0 = idxp[min(gr0, gmax)];
    const int i1 = idxp[min(gr1, gmax)];

    const float* Qg = g_Q + (((size_t)mb * HH + h) * NN) * DH;
    unsigned qa[8][4];
#pragma unroll
    for (int k8 = 0; k8 < 8; k8++) {
        float2 p0 = *(const float2*)(Qg + (size_t)i0 * 64 + k8 * 8 + l4 * 2);
        float2 p1 = *(const float2*)(Qg + (size_t)i1 * 64 + k8 * 8 + l4 * 2);
        qa[k8][0] = __float_as_uint(p0.x);
        qa[k8][2] = __float_as_uint(p0.y);
        qa[k8][1] = __float_as_uint(p1.x);
        qa[k8][3] = __float_as_uint(p1.y);
    }

    float l_0 = 0.f, l_1 = 0.f;
    float o[8][4];
#pragma unroll
    for (int nt = 0; nt < 8; nt++)
#pragma unroll
        for (int e = 0; e < 4; e++) o[nt][e] = 0.f;

    const float* Kg = g_K + (size_t)bh * N3 * DH;
    const float* VTg = g_VT + (size_t)bh * DH * N3;

    auto ldkv_async = [&](int stage, int kt) {
        unsigned* Kst = Ks + stage * KS_W;
        unsigned* Vst = Vs + stage * VS_W;
#pragma unroll
        for (int i = 0; i < 8; i++) {
            int v = tid + i * 128;
            int r = v >> 4, c4 = (v & 15) << 2;
            cpa16(&Kst[r * SK + c4], Kg + (size_t)(kt * 64 + r) * 64 + c4);
            cpa16(&Vst[r * SV + c4], VTg + (size_t)r * N3 + kt * 64 + c4);
        }
    };

    ldkv_async(0, 0);
    CP_COMMIT;

    for (int kt = 0; kt < 24; kt++) {
        if (kt < 23) {
            ldkv_async((kt + 1) & 1, kt + 1);
            CP_COMMIT;
            CP_WAIT1;
        } else {
            CP_WAIT0;
        }
        __syncthreads();

        const unsigned* Kst = Ks + (kt & 1) * KS_W;
        const unsigned* Vst = Vs + (kt & 1) * VS_W;

        // S = Q K^T
        float s[8][4];
#pragma unroll
        for (int nt = 0; nt < 8; nt++)
#pragma unroll
            for (int e = 0; e < 4; e++) s[nt][e] = 0.f;
#pragma unroll
        for (int k8 = 0; k8 < 8; k8++) {
#pragma unroll
            for (int nt = 0; nt < 8; nt++) {
                int key = nt * 8 + grp;
                uint2 bp = *(const uint2*)&Kst[key * SK + k8 * 8 + l4 * 2];
                unsigned bf[2] = {bp.x, bp.y};
                mma8(s[nt], qa[k8], bf);
            }
        }

        // Fixed-max softmax: P = exp(S - FIXMAX), no rescaling of O ever.
        float sum0 = 0.f, sum1 = 0.f;
#pragma unroll
        for (int nt = 0; nt < 8; nt++) {
            s[nt][0] = __expf(s[nt][0] - FIXMAX);
            s[nt][1] = __expf(s[nt][1] - FIXMAX);
            s[nt][2] = __expf(s[nt][2] - FIXMAX);
            s[nt][3] = __expf(s[nt][3] - FIXMAX);
            sum0 += s[nt][0] + s[nt][1];
            sum1 += s[nt][2] + s[nt][3];
        }
        sum0 += __shfl_xor_sync(0xffffffffu, sum0, 1);
        sum0 += __shfl_xor_sync(0xffffffffu, sum0, 2);
        sum1 += __shfl_xor_sync(0xffffffffu, sum1, 1);
        sum1 += __shfl_xor_sync(0xffffffffu, sum1, 2);
        l_0 += sum0;
        l_1 += sum1;

        // O += P @ V  (C-frag -> A-frag via quad shuffles; V^T frags LDS.64)
        const int src = (grp << 2) | (l4 >> 1);
        const bool odd = (l4 & 1);
#pragma unroll
        for (int k8 = 0; k8 < 8; k8++) {
            float t0 = __shfl_sync(0xffffffffu, s[k8][0], src);
            float t1 = __shfl_sync(0xffffffffu, s[k8][1], src);
            float t2 = __shfl_sync(0xffffffffu, s[k8][2], src);
            float t3 = __shfl_sync(0xffffffffu, s[k8][3], src);
            float u0 = __shfl_sync(0xffffffffu, s[k8][0], src + 2);
            float u1 = __shfl_sync(0xffffffffu, s[k8][1], src + 2);
            float u2 = __shfl_sync(0xffffffffu, s[k8][2], src + 2);
            float u3 = __shfl_sync(0xffffffffu, s[k8][3], src + 2);
            unsigned pa[4];
            pa[0] = f2t(odd ? t1 : t0);
            pa[1] = f2t(odd ? t3 : t2);
            pa[2] = f2t(odd ? u1 : u0);
            pa[3] = f2t(odd ? u3 : u2);
#pragma unroll
            for (int nt = 0; nt < 8; nt++) {
                int drow = nt * 8 + grp;
                uint2 bp = *(const uint2*)&Vst[drow * SV + k8 * 8 + l4 * 2];
                unsigned bf[2] = {bp.x, bp.y};
                mma8(o[nt], pa, bf);
            }
        }
        __syncthreads();
    }

    // Epilogue: normalize, tf32-round, scatter to original rows (perm-d cols)
    float linv0 = 1.f / l_0, linv1 = 1.f / l_1;
    size_t base0 = ((size_t)mb * NN + i0) * DI + h * 64;
    size_t base1 = ((size_t)mb * NN + i1) * DI + h * 64;
    const int pd0 = perm8(2 * l4);
    const int pd1 = perm8(2 * l4 + 1);
    if (gr0 < cnt) {
#pragma unroll
        for (int nt = 0; nt < 8; nt++) {
            g_O[base0 + nt * 8 + pd0] = tf32r(o[nt][0] * linv0);
            g_O[base0 + nt * 8 + pd1] = tf32r(o[nt][1] * linv0);
        }
    }
    if (gr1 < cnt) {
#pragma unroll
        for (int nt = 0; nt < 8; nt++) {
            g_O[base1 + nt * 8 + pd0] = tf32r(o[nt][2] * linv1);
            g_O[base1 + nt * 8 + pd1] = tf32r(o[nt][3] * linv1);
        }
    }
}

// ---------------------------------------------------------------------------
// Input order: 0:x0 1:m0 2:Wqkv0 3:Wout0 | 4:x1 5:m1 6:Wqkv1 7:Wout1 | 8:...
// ---------------------------------------------------------------------------
extern "C" void kernel_launch(void* const* d_in, const int* in_sizes, int n_in,
                              void* d_out, int out_size) {
    const float* x0  = (const float*)d_in[0];
    const int*   m0  = (const int*)d_in[1];
    const float* wq0 = (const float*)d_in[2];
    const float* wo0 = (const float*)d_in[3];
    const float* x1  = (const float*)d_in[4];
    const int*   m1  = (const int*)d_in[5];
    const float* wq1 = (const float*)d_in[6];
    const float* wo1 = (const float*)d_in[7];
    const float* x2  = (const float*)d_in[8];
    const int*   m2  = (const int*)d_in[9];
    const float* wq2 = (const float*)d_in[10];
    const float* wo2 = (const float*)d_in[11];
    float* out = (float*)d_out;

    static int configured = 0;
    if (!configured) {
        cudaFuncSetAttribute(gemm_qkv,
                             cudaFuncAttributeMaxDynamicSharedMemorySize, GEMM_SMEM);
        cudaFuncSetAttribute(gemm_out,
                             cudaFuncAttributeMaxDynamicSharedMemorySize, GEMM_SMEM);
        cudaFuncSetAttribute(attn_tc,
                             cudaFuncAttributeMaxDynamicSharedMemorySize, ATT_SMEM);
        configured = 1;
    }

    float *gx, *gwqt, *gwot;
    cudaGetSymbolAddress((void**)&gx, g_X);
    cudaGetSymbolAddress((void**)&gwqt, g_WqT);
    cudaGetSymbolAddress((void**)&gwot, g_WoT);

    prep_x<<<dim3(2048, 3), 256>>>(x0, x1, x2);
    transpose_w<<<dim3(48, 16, 3), dim3(32, 8)>>>(wq0, wq1, wq2, gwqt, 1536);
    transpose_w<<<dim3(16, 16, 3), dim3(32, 8)>>>(wo0, wo1, wo2, gwot, 512);
    compact_mask<<<24, 512>>>(m0, m1, m2);
    gemm_qkv<<<dim3(12, 32, 3), 256, GEMM_SMEM>>>(gx, gwqt);
    mean_v<<<64, 128>>>();
    mvout_gemm<<<24, 512>>>();
    scatter_masked_out<<<dim3(64, 24), 512>>>(m0, m1, m2, out);
    attn_tc<<<dim3(8, 64, 3), 128, ATT_SMEM>>>();
    gemm_out<<<dim3(4, 4, 24), 256, GEMM_SMEM>>>(gwot, out);
}

// round 12
// speedup vs baseline: 1.1586x; 1.0321x over previous
#include <cuda_runtime.h>
#include <math.h>
#include <stdint.h>

#define BB 8
#define NN 512
#define HH 8
#define DH 64
#define DI 512
#define N3 1536
#define SCALE 0.125f
#define FIXMAX 8.0f

// Scratch (device globals). All tf32-exact fp32 bits.
// k-dims of X/W/Q/K stored with in-block perm8 so mma fragment pairs (k, k+4)
// are adjacent (LDS.64). V^T stored UNPERMUTED [bh][d][key]: the S C-fragment
// is reused directly as the P A-fragment (slot-permuted contraction), which
// requires B rows in natural key order.
__device__ float g_X[3ull * 4096 * 512];           // [mod][row][perm k]
__device__ float g_WqT[3ull * 1536 * 512];         // [mod][n][perm k]
__device__ float g_WoT[3ull * 512 * 512];          // [mod][n][perm k]
__device__ float g_Q[3ull * BB * HH * NN * DH];    // [mod][b][h][n][perm d], pre-scaled
__device__ float g_K[(size_t)BB * HH * N3 * DH];   // [bh][key][perm d]
__device__ float g_VT[(size_t)BB * HH * DH * N3];  // [bh][d][key]  (natural order)
__device__ float g_O[3ull * BB * NN * DI];         // [mod][b][n][perm (h*64+d)]
__device__ int   g_idx[24 * 512];                  // unmasked row indices per (mod,b)
__device__ int   g_cnt[24];
__device__ float g_meanV[64 * 64];                 // [bh][d]
__device__ float g_mvout[24 * 512];                // masked-row output per (mod,b)

__device__ __forceinline__ int perm8(int j) { return ((j & 3) << 1) | (j >> 2); }

__device__ __forceinline__ unsigned f2t(float f) {
    unsigned u;
    asm("cvt.rna.tf32.f32 %0, %1;" : "=r"(u) : "f"(f));
    return u;
}
__device__ __forceinline__ float tf32r(float f) { return __uint_as_float(f2t(f)); }

__device__ __forceinline__ void mma8(float d[4], const unsigned a[4], const unsigned b[2]) {
    asm volatile(
        "mma.sync.aligned.m16n8k8.row.col.f32.tf32.tf32.f32 "
        "{%0,%1,%2,%3}, {%4,%5,%6,%7}, {%8,%9}, {%0,%1,%2,%3};"
        : "+f"(d[0]), "+f"(d[1]), "+f"(d[2]), "+f"(d[3])
        : "r"(a[0]), "r"(a[1]), "r"(a[2]), "r"(a[3]), "r"(b[0]), "r"(b[1]));
}

__device__ __forceinline__ void cpa16(unsigned* dst, const float* src) {
    unsigned d = (unsigned)__cvta_generic_to_shared(dst);
    asm volatile("cp.async.cg.shared.global [%0], [%1], 16;\n" ::"r"(d), "l"(src));
}
#define CP_COMMIT asm volatile("cp.async.commit_group;\n" ::)
#define CP_WAIT1 asm volatile("cp.async.wait_group 1;\n" ::)
#define CP_WAIT0 asm volatile("cp.async.wait_group 0;\n" ::)

// ---------------------------------------------------------------------------
// Prep: X tf32-round + perm8 columns. grid (2048, 3), 256 threads.
// ---------------------------------------------------------------------------
__global__ void prep_x(const float* __restrict__ x0, const float* __restrict__ x1,
                       const float* __restrict__ x2) {
    const int mod = blockIdx.y;
    const float* __restrict__ X = (mod == 0) ? x0 : (mod == 1) ? x1 : x2;
    int i = blockIdx.x * 256 + threadIdx.x;
    int o = i * 4;
    int row = o >> 9, c = o & 511;
    int base = c & ~7;
    float v[4];
#pragma unroll
    for (int q = 0; q < 4; q++) {
        int qq = (c + q) & 7;
        int j = ((qq & 1) << 2) | (qq >> 1);     // inverse perm
        v[q] = tf32r(X[(size_t)row * 512 + base + j]);
    }
    *(float4*)(g_X + (size_t)mod * 4096 * 512 + o) = make_float4(v[0], v[1], v[2], v[3]);
}

// Transpose W [512][N] -> WT [mod][N][512], tf32-rounded, perm8 on k.
__global__ void transpose_w(const float* __restrict__ w0, const float* __restrict__ w1,
                            const float* __restrict__ w2, float* __restrict__ dst,
                            int N) {
    __shared__ float t[32][33];
    const int mod = blockIdx.z;
    const float* __restrict__ W = (mod == 0) ? w0 : (mod == 1) ? w1 : w2;
    float* __restrict__ D = dst + (size_t)mod * N * 512;
    const int n0 = blockIdx.x * 32, k0 = blockIdx.y * 32;
    const int tx = threadIdx.x, ty = threadIdx.y;
#pragma unroll
    for (int j = ty; j < 32; j += 8) t[j][tx] = W[(size_t)(k0 + j) * N + n0 + tx];
    __syncthreads();
#pragma unroll
    for (int j = ty; j < 32; j += 8) {
        int pk = (tx & ~7) | perm8(tx & 7);
        D[(size_t)(n0 + j) * 512 + k0 + pk] = tf32r(t[tx][j]);
    }
}

// ---------------------------------------------------------------------------
// Mask compaction: per (mod,b) list of unmasked row indices + count. grid 24.
// ---------------------------------------------------------------------------
__global__ void compact_mask(const int* __restrict__ m0, const int* __restrict__ m1,
                             const int* __restrict__ m2) {
    const int mb = blockIdx.x;
    const int mod = mb >> 3, b = mb & 7;
    const int* __restrict__ M = (mod == 0) ? m0 : (mod == 1) ? m1 : m2;
    const int tid = threadIdx.x;
    const int on = (M[b * NN + tid] != 0) ? 1 : 0;
    const int lane = tid & 31, w = tid >> 5;
    unsigned ball = __ballot_sync(0xffffffffu, on);
    int pre = __popc(ball & ((1u << lane) - 1u));
    __shared__ int wsum[16];
    if (lane == 31) wsum[w] = pre + on;
    __syncthreads();
    if (tid == 0) {
        int acc = 0;
#pragma unroll
        for (int i = 0; i < 16; i++) { int t = wsum[i]; wsum[i] = acc; acc += t; }
        g_cnt[mb] = acc;
    }
    __syncthreads();
    if (on) g_idx[mb * 512 + wsum[w] + pre] = tid;
}

// ---------------------------------------------------------------------------
// meanV: per bh, mean over 1536 keys of V. grid 64, 128 threads.
// ---------------------------------------------------------------------------
__global__ void mean_v() {
    const int bh = blockIdx.x;
    const int d = threadIdx.x >> 1, half = threadIdx.x & 1;
    const float* row = g_VT + (size_t)bh * DH * N3 + (size_t)d * N3 + half * 768;
    float s = 0.f;
#pragma unroll 4
    for (int i = 0; i < 768; i += 4) {
        float4 v = *(const float4*)(row + i);
        s += v.x + v.y + v.z + v.w;
    }
    s += __shfl_xor_sync(0xffffffffu, s, 1);
    if (!half) g_meanV[bh * 64 + d] = s * (1.0f / 1536.0f);
}

// ---------------------------------------------------------------------------
// mvout: masked-row output = meanV @ Wout, per (mod,b). grid 24, 512 threads.
// ---------------------------------------------------------------------------
__global__ void mvout_gemm() {
    const int mb = blockIdx.x;
    const int mod = mb >> 3, b = mb & 7;
    __shared__ float mv[512];
    const int tid = threadIdx.x;
    {
        int h = tid >> 6, d = tid & 63;
        int pk = (tid & ~7) | perm8(tid & 7);
        mv[pk] = g_meanV[(b * HH + h) * 64 + d];
    }
    __syncthreads();
    const float* w = g_WoT + (size_t)mod * 512 * 512 + (size_t)tid * 512;
    float s = 0.f;
#pragma unroll 4
    for (int k = 0; k < 512; k += 4) {
        float4 wv = *(const float4*)(w + k);
        s += wv.x * mv[k] + wv.y * mv[k + 1] + wv.z * mv[k + 2] + wv.w * mv[k + 3];
    }
    g_mvout[mb * 512 + tid] = s;
}

// ---------------------------------------------------------------------------
// scatter_masked_out: broadcast mvout into masked output rows.
// grid (64, 24), 512 threads; 8 rows per block.
// ---------------------------------------------------------------------------
__global__ void scatter_masked_out(const int* __restrict__ m0, const int* __restrict__ m1,
                                   const int* __restrict__ m2, float* __restrict__ out) {
    const int mb = blockIdx.y;
    const int mod = mb >> 3, b = mb & 7;
    const int* __restrict__ M = (mod == 0) ? m0 : (mod == 1) ? m1 : m2;
    const int tid = threadIdx.x;
    const float v = g_mvout[mb * 512 + tid];
#pragma unroll
    for (int r = 0; r < 8; r++) {
        int n = blockIdx.x * 8 + r;
        if (M[b * NN + n] == 0)
            out[((size_t)mod * 4096 + b * NN + n) * 512 + tid] = v;
    }
}

// ---------------------------------------------------------------------------
// Tensor-core GEMM (QKV): 2-stage cp.async (80KB smem -> 2 CTAs/SM).
// Tile 128x128, 256 thr, k-chunk 32, LDS.64 fragments both operands.
// ---------------------------------------------------------------------------
#define SA 40
#define SBT 40
#define XS_W (128 * SA)
#define WS_W (128 * SBT)
#define GEMM_SMEM (2 * (XS_W + WS_W) * 4)

__global__ __launch_bounds__(256) void gemm_qkv(const float* __restrict__ Xbase,
                                                const float* __restrict__ WTbase) {
    extern __shared__ unsigned sh[];
    unsigned* Xs = sh;                  // 2 stages
    unsigned* Ws = sh + 2 * XS_W;

    const int mod = blockIdx.z;
    const float* __restrict__ X = Xbase + (size_t)mod * 4096 * 512;
    const float* __restrict__ WT = WTbase + (size_t)mod * 1536 * 512;

    const int tid = threadIdx.x;
    const int wid = tid >> 5, lane = tid & 31;
    const int grp = lane >> 2, l4 = lane & 3;
    const int wm = wid >> 2, wn = wid & 3;
    const int rowbase = blockIdx.y * 128;
    const int colbase = blockIdx.x * 128;

    float c[4][4][4];
#pragma unroll
    for (int mt = 0; mt < 4; mt++)
#pragma unroll
        for (int nt = 0; nt < 4; nt++)
#pragma unroll
            for (int e = 0; e < 4; e++) c[mt][nt][e] = 0.f;

    const int rr = tid >> 3, cc = (tid & 7) << 2;

    auto ldg_async = [&](int stage, int k0) {
        unsigned* Xst = Xs + stage * XS_W;
        unsigned* Wst = Ws + stage * WS_W;
#pragma unroll
        for (int i = 0; i < 4; i++) {
            cpa16(&Xst[(rr + i * 32) * SA + cc],
                  X + (size_t)(rowbase + rr + i * 32) * 512 + k0 + cc);
            cpa16(&Wst[(rr + i * 32) * SBT + cc],
                  WT + (size_t)(colbase + rr + i * 32) * 512 + k0 + cc);
        }
    };

    ldg_async(0, 0);
    CP_COMMIT;

    for (int chunk = 0; chunk < 16; chunk++) {
        if (chunk < 15) {
            ldg_async((chunk + 1) & 1, (chunk + 1) * 32);
            CP_COMMIT;
            CP_WAIT1;
        } else {
            CP_WAIT0;
        }
        __syncthreads();

        const unsigned* Xst = Xs + (chunk & 1) * XS_W;
        const unsigned* Wst = Ws + (chunk & 1) * WS_W;
#pragma unroll
        for (int k8 = 0; k8 < 4; k8++) {
            unsigned a[4][4];
#pragma unroll
            for (int mt = 0; mt < 4; mt++) {
                int r0 = wm * 64 + mt * 16 + grp;
                uint2 p0 = *(const uint2*)&Xst[r0 * SA + k8 * 8 + l4 * 2];
                uint2 p1 = *(const uint2*)&Xst[(r0 + 8) * SA + k8 * 8 + l4 * 2];
                a[mt][0] = p0.x; a[mt][2] = p0.y;
                a[mt][1] = p1.x; a[mt][3] = p1.y;
            }
#pragma unroll
            for (int nt = 0; nt < 4; nt++) {
                int col = wn * 32 + nt * 8 + grp;
                uint2 bp = *(const uint2*)&Wst[col * SBT + k8 * 8 + l4 * 2];
                unsigned b[2] = {bp.x, bp.y};
#pragma unroll
                for (int mt = 0; mt < 4; mt++) mma8(c[mt][nt], a[mt], b);
            }
        }
        __syncthreads();
    }

    // Epilogue: QKV scatter.  Q/K: perm-d.  V^T: NATURAL key order.
#pragma unroll
    for (int mt = 0; mt < 4; mt++) {
        int gr0 = rowbase + wm * 64 + mt * 16 + grp;
        int gr1 = gr0 + 8;
#pragma unroll
        for (int nt = 0; nt < 4; nt++) {
            int gc = colbase + wn * 32 + nt * 8 + l4 * 2;
#pragma unroll
            for (int e = 0; e < 4; e++) {
                int gr = (e < 2) ? gr0 : gr1;
                int gcc = gc + (e & 1);
                float v = c[mt][nt][e];
                int b = gr >> 9, n = gr & 511;
                if (gcc < 512) {
                    int h = gcc >> 6, dd = gcc & 63;
                    int pd = (dd & ~7) | perm8(dd & 7);
                    g_Q[((((size_t)mod * BB + b) * HH + h) * NN + n) * DH + pd] =
                        tf32r(v * SCALE);
                } else if (gcc < 1024) {
                    int c2 = gcc - 512, h = c2 >> 6, dd = c2 & 63;
                    int pd = (dd & ~7) | perm8(dd & 7);
                    g_K[(((size_t)b * HH + h) * N3 + mod * NN + n) * DH + pd] = tf32r(v);
                } else {
                    int c2 = gcc - 1024, h = c2 >> 6, dd = c2 & 63;
                    int key = mod * NN + n;
                    g_VT[(((size_t)b * HH + h) * DH + dd) * N3 + key] = tf32r(v);
                }
            }
        }
    }
}

// ---------------------------------------------------------------------------
// Out GEMM over COMPACTED rows: out[rows] = g_O[gathered] @ Wout (WT form).
// grid (4 coltiles, 4 rowtiles, 24 mb), 256 thr, 2-stage, early-exit.
// ---------------------------------------------------------------------------
__global__ __launch_bounds__(256) void gemm_out(const float* __restrict__ WTbase,
                                                float* __restrict__ out) {
    extern __shared__ unsigned sh[];
    unsigned* Xs = sh;
    unsigned* Ws = sh + 2 * XS_W;

    const int mb = blockIdx.z;
    const int mod = mb >> 3, b = mb & 7;
    const int cnt = g_cnt[mb];
    const int rowbase = blockIdx.y * 128;
    if (rowbase >= cnt) return;
    const int colbase = blockIdx.x * 128;
    const int gmax = cnt - 1;
    const int* idxp = g_idx + mb * 512;

    const float* __restrict__ Xg = g_O + (size_t)mb * NN * DI;
    const float* __restrict__ WT = WTbase + (size_t)mod * 512 * 512;

    const int tid = threadIdx.x;
    const int wid = tid >> 5, lane = tid & 31;
    const int grp = lane >> 2, l4 = lane & 3;
    const int wm = wid >> 2, wn = wid & 3;

    float c[4][4][4];
#pragma unroll
    for (int mt = 0; mt < 4; mt++)
#pragma unroll
        for (int nt = 0; nt < 4; nt++)
#pragma unroll
            for (int e = 0; e < 4; e++) c[mt][nt][e] = 0.f;

    const int rr = tid >> 3, cc = (tid & 7) << 2;

    const float* arow[4];
#pragma unroll
    for (int i = 0; i < 4; i++)
        arow[i] = Xg + (size_t)idxp[min(rowbase + rr + i * 32, gmax)] * DI;

    auto ldg_async = [&](int stage, int k0) {
        unsigned* Xst = Xs + stage * XS_W;
        unsigned* Wst = Ws + stage * WS_W;
#pragma unroll
        for (int i = 0; i < 4; i++) {
            cpa16(&Xst[(rr + i * 32) * SA + cc], arow[i] + k0 + cc);
            cpa16(&Wst[(rr + i * 32) * SBT + cc],
                  WT + (size_t)(colbase + rr + i * 32) * 512 + k0 + cc);
        }
    };

    ldg_async(0, 0);
    CP_COMMIT;

    for (int chunk = 0; chunk < 16; chunk++) {
        if (chunk < 15) {
            ldg_async((chunk + 1) & 1, (chunk + 1) * 32);
            CP_COMMIT;
            CP_WAIT1;
        } else {
            CP_WAIT0;
        }
        __syncthreads();

        const unsigned* Xst = Xs + (chunk & 1) * XS_W;
        const unsigned* Wst = Ws + (chunk & 1) * WS_W;
#pragma unroll
        for (int k8 = 0; k8 < 4; k8++) {
            unsigned a[4][4];
#pragma unroll
            for (int mt = 0; mt < 4; mt++) {
                int r0 = wm * 64 + mt * 16 + grp;
                uint2 p0 = *(const uint2*)&Xst[r0 * SA + k8 * 8 + l4 * 2];
                uint2 p1 = *(const uint2*)&Xst[(r0 + 8) * SA + k8 * 8 + l4 * 2];
                a[mt][0] = p0.x; a[mt][2] = p0.y;
                a[mt][1] = p1.x; a[mt][3] = p1.y;
            }
#pragma unroll
            for (int nt = 0; nt < 4; nt++) {
                int col = wn * 32 + nt * 8 + grp;
                uint2 bp = *(const uint2*)&Wst[col * SBT + k8 * 8 + l4 * 2];
                unsigned bb[2] = {bp.x, bp.y};
#pragma unroll
                for (int mt = 0; mt < 4; mt++) mma8(c[mt][nt], a[mt], bb);
            }
        }
        __syncthreads();
    }

    // Epilogue: scatter to original output rows (guarded)
#pragma unroll
    for (int mt = 0; mt < 4; mt++) {
        int gr0 = rowbase + wm * 64 + mt * 16 + grp;   // compacted indices
        int gr1 = gr0 + 8;
#pragma unroll
        for (int nt = 0; nt < 4; nt++) {
            int gc = colbase + wn * 32 + nt * 8 + l4 * 2;
            if (gr0 < cnt) {
                size_t orow = (size_t)mod * 4096 + b * NN + idxp[gr0];
                *(float2*)(out + orow * 512 + gc) = make_float2(c[mt][nt][0], c[mt][nt][1]);
            }
            if (gr1 < cnt) {
                size_t orow = (size_t)mod * 4096 + b * NN + idxp[gr1];
                *(float2*)(out + orow * 512 + gc) = make_float2(c[mt][nt][2], c[mt][nt][3]);
            }
        }
    }
}

// ---------------------------------------------------------------------------
// Flash attention over compacted rows, FIXED-MAX softmax, SHUFFLE-FREE P->A:
// the S C-fragment is reused directly as the P A-fragment (slot permutation
// matched by V^T natural-key storage). grid (8, 64, 3), 128 thr.
// ---------------------------------------------------------------------------
#define SK 72
#define SV 72
#define KS_W (64 * SK)
#define VS_W (64 * SV)
#define ATT_SMEM ((2 * KS_W + 2 * VS_W) * 4)

__global__ __launch_bounds__(128, 3) void attn_tc() {
    extern __shared__ unsigned sh[];
    unsigned* Ks = sh;
    unsigned* Vs = sh + 2 * KS_W;

    const int mod = blockIdx.z;
    const int bh = blockIdx.y;
    const int b = bh >> 3, h = bh & 7;
    const int qt = blockIdx.x;
    const int mb = mod * 8 + b;

    const int cnt = g_cnt[mb];
    if (qt * 64 >= cnt) return;

    const int tid = threadIdx.x;
    const int wid = tid >> 5, lane = tid & 31;
    const int grp = lane >> 2, l4 = lane & 3;

    const int r0 = wid * 16 + grp;
    const int r1 = r0 + 8;
    const int gr0 = qt * 64 + r0, gr1 = qt * 64 + r1;
    const int gmax = cnt - 1;
    const int* idxp = g_idx + mb * 512;
    const int i0 = idxp[min(gr0, gmax)];
    const int i1 = idxp[min(gr1, gmax)];

    const float* Qg = g_Q + (((size_t)mb * HH + h) * NN) * DH;
    unsigned qa[8][4];
#pragma unroll
    for (int k8 = 0; k8 < 8; k8++) {
        float2 p0 = *(const float2*)(Qg + (size_t)i0 * 64 + k8 * 8 + l4 * 2);
        float2 p1 = *(const float2*)(Qg + (size_t)i1 * 64 + k8 * 8 + l4 * 2);
        qa[k8][0] = __float_as_uint(p0.x);
        qa[k8][2] = __float_as_uint(p0.y);
        qa[k8][1] = __float_as_uint(p1.x);
        qa[k8][3] = __float_as_uint(p1.y);
    }

    float l_0 = 0.f, l_1 = 0.f;
    float o[8][4];
#pragma unroll
    for (int nt = 0; nt < 8; nt++)
#pragma unroll
        for (int e = 0; e < 4; e++) o[nt][e] = 0.f;

    const float* Kg = g_K + (size_t)bh * N3 * DH;
    const float* VTg = g_VT + (size_t)bh * DH * N3;

    auto ldkv_async = [&](int stage, int kt) {
        unsigned* Kst = Ks + stage * KS_W;
        unsigned* Vst = Vs + stage * VS_W;
#pragma unroll
        for (int i = 0; i < 8; i++) {
            int v = tid + i * 128;
            int r = v >> 4, c4 = (v & 15) << 2;
            cpa16(&Kst[r * SK + c4], Kg + (size_t)(kt * 64 + r) * 64 + c4);
            cpa16(&Vst[r * SV + c4], VTg + (size_t)r * N3 + kt * 64 + c4);
        }
    };

    ldkv_async(0, 0);
    CP_COMMIT;

    for (int kt = 0; kt < 24; kt++) {
        if (kt < 23) {
            ldkv_async((kt + 1) & 1, kt + 1);
            CP_COMMIT;
            CP_WAIT1;
        } else {
            CP_WAIT0;
        }
        __syncthreads();

        const unsigned* Kst = Ks + (kt & 1) * KS_W;
        const unsigned* Vst = Vs + (kt & 1) * VS_W;

        // S = Q K^T
        float s[8][4];
#pragma unroll
        for (int nt = 0; nt < 8; nt++)
#pragma unroll
            for (int e = 0; e < 4; e++) s[nt][e] = 0.f;
#pragma unroll
        for (int k8 = 0; k8 < 8; k8++) {
#pragma unroll
            for (int nt = 0; nt < 8; nt++) {
                int key = nt * 8 + grp;
                uint2 bp = *(const uint2*)&Kst[key * SK + k8 * 8 + l4 * 2];
                unsigned bf[2] = {bp.x, bp.y};
                mma8(s[nt], qa[k8], bf);
            }
        }

        // Fixed-max softmax: P = exp(S - FIXMAX), no rescaling of O ever.
        float sum0 = 0.f, sum1 = 0.f;
#pragma unroll
        for (int nt = 0; nt < 8; nt++) {
            s[nt][0] = __expf(s[nt][0] - FIXMAX);
            s[nt][1] = __expf(s[nt][1] - FIXMAX);
            s[nt][2] = __expf(s[nt][2] - FIXMAX);
            s[nt][3] = __expf(s[nt][3] - FIXMAX);
            sum0 += s[nt][0] + s[nt][1];
            sum1 += s[nt][2] + s[nt][3];
        }
        sum0 += __shfl_xor_sync(0xffffffffu, sum0, 1);
        sum0 += __shfl_xor_sync(0xffffffffu, sum0, 2);
        sum1 += __shfl_xor_sync(0xffffffffu, sum1, 1);
        sum1 += __shfl_xor_sync(0xffffffffu, sum1, 2);
        l_0 += sum0;
        l_1 += sum1;

        // O += P @ V  — S C-frag reused directly as A-frag (no shuffles).
        // Slot l4 holds key 2*l4, slot l4+4 holds key 2*l4+1; V^T rows are in
        // natural key order so B slots pair identically.
#pragma unroll
        for (int k8 = 0; k8 < 8; k8++) {
            unsigned pa[4];
            pa[0] = f2t(s[k8][0]);
            pa[1] = f2t(s[k8][2]);
            pa[2] = f2t(s[k8][1]);
            pa[3] = f2t(s[k8][3]);
#pragma unroll
            for (int nt = 0; nt < 8; nt++) {
                int drow = nt * 8 + grp;
                uint2 bp = *(const uint2*)&Vst[drow * SV + k8 * 8 + l4 * 2];
                unsigned bf[2] = {bp.x, bp.y};
                mma8(o[nt], pa, bf);
            }
        }
        __syncthreads();
    }

    // Epilogue: normalize, tf32-round, scatter to original rows (perm-d cols)
    float linv0 = 1.f / l_0, linv1 = 1.f / l_1;
    size_t base0 = ((size_t)mb * NN + i0) * DI + h * 64;
    size_t base1 = ((size_t)mb * NN + i1) * DI + h * 64;
    const int pd0 = perm8(2 * l4);
    const int pd1 = perm8(2 * l4 + 1);
    if (gr0 < cnt) {
#pragma unroll
        for (int nt = 0; nt < 8; nt++) {
            g_O[base0 + nt * 8 + pd0] = tf32r(o[nt][0] * linv0);
            g_O[base0 + nt * 8 + pd1] = tf32r(o[nt][1] * linv0);
        }
    }
    if (gr1 < cnt) {
#pragma unroll
        for (int nt = 0; nt < 8; nt++) {
            g_O[base1 + nt * 8 + pd0] = tf32r(o[nt][2] * linv1);
            g_O[base1 + nt * 8 + pd1] = tf32r(o[nt][3] * linv1);
        }
    }
}

// ---------------------------------------------------------------------------
// Input order: 0:x0 1:m0 2:Wqkv0 3:Wout0 | 4:x1 5:m1 6:Wqkv1 7:Wout1 | 8:...
// ---------------------------------------------------------------------------
extern "C" void kernel_launch(void* const* d_in, const int* in_sizes, int n_in,
                              void* d_out, int out_size) {
    const float* x0  = (const float*)d_in[0];
    const int*   m0  = (const int*)d_in[1];
    const float* wq0 = (const float*)d_in[2];
    const float* wo0 = (const float*)d_in[3];
    const float* x1  = (const float*)d_in[4];
    const int*   m1  = (const int*)d_in[5];
    const float* wq1 = (const float*)d_in[6];
    const float* wo1 = (const float*)d_in[7];
    const float* x2  = (const float*)d_in[8];
    const int*   m2  = (const int*)d_in[9];
    const float* wq2 = (const float*)d_in[10];
    const float* wo2 = (const float*)d_in[11];
    float* out = (float*)d_out;

    static int configured = 0;
    if (!configured) {
        cudaFuncSetAttribute(gemm_qkv,
                             cudaFuncAttributeMaxDynamicSharedMemorySize, GEMM_SMEM);
        cudaFuncSetAttribute(gemm_out,
                             cudaFuncAttributeMaxDynamicSharedMemorySize, GEMM_SMEM);
        cudaFuncSetAttribute(attn_tc,
                             cudaFuncAttributeMaxDynamicSharedMemorySize, ATT_SMEM);
        configured = 1;
    }

    float *gx, *gwqt, *gwot;
    cudaGetSymbolAddress((void**)&gx, g_X);
    cudaGetSymbolAddress((void**)&gwqt, g_WqT);
    cudaGetSymbolAddress((void**)&gwot, g_WoT);

    prep_x<<<dim3(2048, 3), 256>>>(x0, x1, x2);
    transpose_w<<<dim3(48, 16, 3), dim3(32, 8)>>>(wq0, wq1, wq2, gwqt, 1536);
    transpose_w<<<dim3(16, 16, 3), dim3(32, 8)>>>(wo0, wo1, wo2, gwot, 512);
    compact_mask<<<24, 512>>>(m0, m1, m2);
    gemm_qkv<<<dim3(12, 32, 3), 256, GEMM_SMEM>>>(gx, gwqt);
    mean_v<<<64, 128>>>();
    mvout_gemm<<<24, 512>>>();
    scatter_masked_out<<<dim3(64, 24), 512>>>(m0, m1, m2, out);
    attn_tc<<<dim3(8, 64, 3), 128, ATT_SMEM>>>();
    gemm_out<<<dim3(4, 4, 24), 256, GEMM_SMEM>>>(gwot, out);
}

// round 13
// speedup vs baseline: 1.1686x; 1.0087x over previous
#include <cuda_runtime.h>
#include <math.h>
#include <stdint.h>

#define BB 8
#define NN 512
#define HH 8
#define DH 64
#define DI 512
#define N3 1536
#define SCALE 0.125f
#define FIXMAX 8.0f

// Scratch (device globals). All tf32-exact fp32 bits.
// k-dims of X/W/Q/K stored with in-block perm8 so mma fragment pairs (k, k+4)
// are adjacent (LDS.64). V^T stored UNPERMUTED [bh][d][key]: the S C-fragment
// is reused directly as the P A-fragment (slot-permuted contraction).
__device__ float g_X[3ull * 4096 * 512];           // [mod][row][perm k]
__device__ float g_WqT[3ull * 1536 * 512];         // [mod][n][perm k]
__device__ float g_WoT[3ull * 512 * 512];          // [mod][n][perm k]
__device__ float g_Q[3ull * BB * HH * NN * DH];    // [mod][b][h][n][perm d], pre-scaled
__device__ float g_K[(size_t)BB * HH * N3 * DH];   // [bh][key][perm d]
__device__ float g_VT[(size_t)BB * HH * DH * N3];  // [bh][d][key]  (natural order)
__device__ float g_O[3ull * BB * NN * DI];         // [mod][b][n][perm (h*64+d)]
__device__ int   g_idx[24 * 512];                  // unmasked row indices per (mod,b)
__device__ int   g_cnt[24];
__device__ float g_meanV[64 * 64];                 // [bh][d]
__device__ float g_mvout[24 * 512];                // masked-row output per (mod,b)

__device__ __forceinline__ int perm8(int j) { return ((j & 3) << 1) | (j >> 2); }

__device__ __forceinline__ unsigned f2t(float f) {
    unsigned u;
    asm("cvt.rna.tf32.f32 %0, %1;" : "=r"(u) : "f"(f));
    return u;
}
__device__ __forceinline__ float tf32r(float f) { return __uint_as_float(f2t(f)); }

__device__ __forceinline__ void mma8(float d[4], const unsigned a[4], const unsigned b[2]) {
    asm volatile(
        "mma.sync.aligned.m16n8k8.row.col.f32.tf32.tf32.f32 "
        "{%0,%1,%2,%3}, {%4,%5,%6,%7}, {%8,%9}, {%0,%1,%2,%3};"
        : "+f"(d[0]), "+f"(d[1]), "+f"(d[2]), "+f"(d[3])
        : "r"(a[0]), "r"(a[1]), "r"(a[2]), "r"(a[3]), "r"(b[0]), "r"(b[1]));
}

__device__ __forceinline__ void cpa16(unsigned* dst, const float* src) {
    unsigned d = (unsigned)__cvta_generic_to_shared(dst);
    asm volatile("cp.async.cg.shared.global [%0], [%1], 16;\n" ::"r"(d), "l"(src));
}
#define CP_COMMIT asm volatile("cp.async.commit_group;\n" ::)
#define CP_WAIT1 asm volatile("cp.async.wait_group 1;\n" ::)
#define CP_WAIT0 asm volatile("cp.async.wait_group 0;\n" ::)

// ---------------------------------------------------------------------------
// Prep: X tf32-round + perm8 columns. grid (2048, 3), 256 threads.
// ---------------------------------------------------------------------------
__global__ void prep_x(const float* __restrict__ x0, const float* __restrict__ x1,
                       const float* __restrict__ x2) {
    const int mod = blockIdx.y;
    const float* __restrict__ X = (mod == 0) ? x0 : (mod == 1) ? x1 : x2;
    int i = blockIdx.x * 256 + threadIdx.x;
    int o = i * 4;
    int row = o >> 9, c = o & 511;
    int base = c & ~7;
    float v[4];
#pragma unroll
    for (int q = 0; q < 4; q++) {
        int qq = (c + q) & 7;
        int j = ((qq & 1) << 2) | (qq >> 1);     // inverse perm
        v[q] = tf32r(X[(size_t)row * 512 + base + j]);
    }
    *(float4*)(g_X + (size_t)mod * 4096 * 512 + o) = make_float4(v[0], v[1], v[2], v[3]);
}

// Transpose W [512][N] -> WT [mod][N][512], tf32-rounded, perm8 on k.
// Fused: z in [0,3) = Wqkv (N=1536), z in [3,6) = Wout (N=512, x<16).
__global__ void transpose_w(const float* __restrict__ wq0, const float* __restrict__ wq1,
                            const float* __restrict__ wq2, const float* __restrict__ wo0,
                            const float* __restrict__ wo1, const float* __restrict__ wo2) {
    __shared__ float t[32][33];
    const int z = blockIdx.z;
    const int mod = (z < 3) ? z : z - 3;
    const int N = (z < 3) ? 1536 : 512;
    if (blockIdx.x * 32 >= N) return;
    const float* __restrict__ W =
        (z == 0) ? wq0 : (z == 1) ? wq1 : (z == 2) ? wq2
        : (z == 3) ? wo0 : (z == 4) ? wo1 : wo2;
    float* __restrict__ D = ((z < 3) ? g_WqT : g_WoT) + (size_t)mod * N * 512;
    const int n0 = blockIdx.x * 32, k0 = blockIdx.y * 32;
    const int tx = threadIdx.x, ty = threadIdx.y;
#pragma unroll
    for (int j = ty; j < 32; j += 8) t[j][tx] = W[(size_t)(k0 + j) * N + n0 + tx];
    __syncthreads();
#pragma unroll
    for (int j = ty; j < 32; j += 8) {
        int pk = (tx & ~7) | perm8(tx & 7);
        D[(size_t)(n0 + j) * 512 + k0 + pk] = tf32r(t[tx][j]);
    }
}

// ---------------------------------------------------------------------------
// Mask compaction: per (mod,b) list of unmasked row indices + count. grid 24.
// ---------------------------------------------------------------------------
__global__ void compact_mask(const int* __restrict__ m0, const int* __restrict__ m1,
                             const int* __restrict__ m2) {
    const int mb = blockIdx.x;
    const int mod = mb >> 3, b = mb & 7;
    const int* __restrict__ M = (mod == 0) ? m0 : (mod == 1) ? m1 : m2;
    const int tid = threadIdx.x;
    const int on = (M[b * NN + tid] != 0) ? 1 : 0;
    const int lane = tid & 31, w = tid >> 5;
    unsigned ball = __ballot_sync(0xffffffffu, on);
    int pre = __popc(ball & ((1u << lane) - 1u));
    __shared__ int wsum[16];
    if (lane == 31) wsum[w] = pre + on;
    __syncthreads();
    if (tid == 0) {
        int acc = 0;
#pragma unroll
        for (int i = 0; i < 16; i++) { int t = wsum[i]; wsum[i] = acc; acc += t; }
        g_cnt[mb] = acc;
    }
    __syncthreads();
    if (on) g_idx[mb * 512 + wsum[w] + pre] = tid;
}

// ---------------------------------------------------------------------------
// meanV: per bh, mean over 1536 keys of V. grid 64, 128 threads.
// ---------------------------------------------------------------------------
__global__ void mean_v() {
    const int bh = blockIdx.x;
    const int d = threadIdx.x >> 1, half = threadIdx.x & 1;
    const float* row = g_VT + (size_t)bh * DH * N3 + (size_t)d * N3 + half * 768;
    float s = 0.f;
#pragma unroll 4
    for (int i = 0; i < 768; i += 4) {
        float4 v = *(const float4*)(row + i);
        s += v.x + v.y + v.z + v.w;
    }
    s += __shfl_xor_sync(0xffffffffu, s, 1);
    if (!half) g_meanV[bh * 64 + d] = s * (1.0f / 1536.0f);
}

// ---------------------------------------------------------------------------
// mvout: masked-row output = meanV @ Wout, per (mod,b). grid 24, 512 threads.
// ---------------------------------------------------------------------------
__global__ void mvout_gemm() {
    const int mb = blockIdx.x;
    const int mod = mb >> 3, b = mb & 7;
    __shared__ float mv[512];
    const int tid = threadIdx.x;
    {
        int h = tid >> 6, d = tid & 63;
        int pk = (tid & ~7) | perm8(tid & 7);
        mv[pk] = g_meanV[(b * HH + h) * 64 + d];
    }
    __syncthreads();
    const float* w = g_WoT + (size_t)mod * 512 * 512 + (size_t)tid * 512;
    float s = 0.f;
#pragma unroll 4
    for (int k = 0; k < 512; k += 4) {
        float4 wv = *(const float4*)(w + k);
        s += wv.x * mv[k] + wv.y * mv[k + 1] + wv.z * mv[k + 2] + wv.w * mv[k + 3];
    }
    g_mvout[mb * 512 + tid] = s;
}

// ---------------------------------------------------------------------------
// scatter_masked_out: broadcast mvout into masked output rows.
// grid (64, 24), 512 threads; 8 rows per block.
// ---------------------------------------------------------------------------
__global__ void scatter_masked_out(const int* __restrict__ m0, const int* __restrict__ m1,
                                   const int* __restrict__ m2, float* __restrict__ out) {
    const int mb = blockIdx.y;
    const int mod = mb >> 3, b = mb & 7;
    const int* __restrict__ M = (mod == 0) ? m0 : (mod == 1) ? m1 : m2;
    const int tid = threadIdx.x;
    const float v = g_mvout[mb * 512 + tid];
#pragma unroll
    for (int r = 0; r < 8; r++) {
        int n = blockIdx.x * 8 + r;
        if (M[b * NN + n] == 0)
            out[((size_t)mod * 4096 + b * NN + n) * 512 + tid] = v;
    }
}

// ---------------------------------------------------------------------------
// Tensor-core GEMM (QKV): 2-stage cp.async (80KB smem -> 2 CTAs/SM).
// Tile 128x128, 256 thr, k-chunk 32, LDS.64 fragments both operands.
// ---------------------------------------------------------------------------
#define SA 40
#define SBT 40
#define XS_W (128 * SA)
#define WS_W (128 * SBT)
#define GEMM_SMEM (2 * (XS_W + WS_W) * 4)

__global__ __launch_bounds__(256) void gemm_qkv(const float* __restrict__ Xbase,
                                                const float* __restrict__ WTbase) {
    extern __shared__ unsigned sh[];
    unsigned* Xs = sh;                  // 2 stages
    unsigned* Ws = sh + 2 * XS_W;

    const int mod = blockIdx.z;
    const float* __restrict__ X = Xbase + (size_t)mod * 4096 * 512;
    const float* __restrict__ WT = WTbase + (size_t)mod * 1536 * 512;

    const int tid = threadIdx.x;
    const int wid = tid >> 5, lane = tid & 31;
    const int grp = lane >> 2, l4 = lane & 3;
    const int wm = wid >> 2, wn = wid & 3;
    const int rowbase = blockIdx.y * 128;
    const int colbase = blockIdx.x * 128;

    float c[4][4][4];
#pragma unroll
    for (int mt = 0; mt < 4; mt++)
#pragma unroll
        for (int nt = 0; nt < 4; nt++)
#pragma unroll
            for (int e = 0; e < 4; e++) c[mt][nt][e] = 0.f;

    const int rr = tid >> 3, cc = (tid & 7) << 2;

    auto ldg_async = [&](int stage, int k0) {
        unsigned* Xst = Xs + stage * XS_W;
        unsigned* Wst = Ws + stage * WS_W;
#pragma unroll
        for (int i = 0; i < 4; i++) {
            cpa16(&Xst[(rr + i * 32) * SA + cc],
                  X + (size_t)(rowbase + rr + i * 32) * 512 + k0 + cc);
            cpa16(&Wst[(rr + i * 32) * SBT + cc],
                  WT + (size_t)(colbase + rr + i * 32) * 512 + k0 + cc);
        }
    };

    ldg_async(0, 0);
    CP_COMMIT;

    for (int chunk = 0; chunk < 16; chunk++) {
        if (chunk < 15) {
            ldg_async((chunk + 1) & 1, (chunk + 1) * 32);
            CP_COMMIT;
            CP_WAIT1;
        } else {
            CP_WAIT0;
        }
        __syncthreads();

        const unsigned* Xst = Xs + (chunk & 1) * XS_W;
        const unsigned* Wst = Ws + (chunk & 1) * WS_W;
#pragma unroll
        for (int k8 = 0; k8 < 4; k8++) {
            unsigned a[4][4];
#pragma unroll
            for (int mt = 0; mt < 4; mt++) {
                int r0 = wm * 64 + mt * 16 + grp;
                uint2 p0 = *(const uint2*)&Xst[r0 * SA + k8 * 8 + l4 * 2];
                uint2 p1 = *(const uint2*)&Xst[(r0 + 8) * SA + k8 * 8 + l4 * 2];
                a[mt][0] = p0.x; a[mt][2] = p0.y;
                a[mt][1] = p1.x; a[mt][3] = p1.y;
            }
#pragma unroll
            for (int nt = 0; nt < 4; nt++) {
                int col = wn * 32 + nt * 8 + grp;
                uint2 bp = *(const uint2*)&Wst[col * SBT + k8 * 8 + l4 * 2];
                unsigned b[2] = {bp.x, bp.y};
#pragma unroll
                for (int mt = 0; mt < 4; mt++) mma8(c[mt][nt], a[mt], b);
            }
        }
        __syncthreads();
    }

    // Epilogue: QKV scatter.  Q/K: perm-d.  V^T: NATURAL key order.
#pragma unroll
    for (int mt = 0; mt < 4; mt++) {
        int gr0 = rowbase + wm * 64 + mt * 16 + grp;
        int gr1 = gr0 + 8;
#pragma unroll
        for (int nt = 0; nt < 4; nt++) {
            int gc = colbase + wn * 32 + nt * 8 + l4 * 2;
#pragma unroll
            for (int e = 0; e < 4; e++) {
                int gr = (e < 2) ? gr0 : gr1;
                int gcc = gc + (e & 1);
                float v = c[mt][nt][e];
                int b = gr >> 9, n = gr & 511;
                if (gcc < 512) {
                    int h = gcc >> 6, dd = gcc & 63;
                    int pd = (dd & ~7) | perm8(dd & 7);
                    g_Q[((((size_t)mod * BB + b) * HH + h) * NN + n) * DH + pd] =
                        tf32r(v * SCALE);
                } else if (gcc < 1024) {
                    int c2 = gcc - 512, h = c2 >> 6, dd = c2 & 63;
                    int pd = (dd & ~7) | perm8(dd & 7);
                    g_K[(((size_t)b * HH + h) * N3 + mod * NN + n) * DH + pd] = tf32r(v);
                } else {
                    int c2 = gcc - 1024, h = c2 >> 6, dd = c2 & 63;
                    int key = mod * NN + n;
                    g_VT[(((size_t)b * HH + h) * DH + dd) * N3 + key] = tf32r(v);
                }
            }
        }
    }
}

// ---------------------------------------------------------------------------
// Out GEMM over COMPACTED rows: out[rows] = g_O[gathered] @ Wout (WT form).
// grid (4 coltiles, 4 rowtiles, 24 mb), 256 thr, 2-stage, early-exit.
// ---------------------------------------------------------------------------
__global__ __launch_bounds__(256) void gemm_out(const float* __restrict__ WTbase,
                                                float* __restrict__ out) {
    extern __shared__ unsigned sh[];
    unsigned* Xs = sh;
    unsigned* Ws = sh + 2 * XS_W;

    const int mb = blockIdx.z;
    const int mod = mb >> 3, b = mb & 7;
    const int cnt = g_cnt[mb];
    const int rowbase = blockIdx.y * 128;
    if (rowbase >= cnt) return;
    const int colbase = blockIdx.x * 128;
    const int gmax = cnt - 1;
    const int* idxp = g_idx + mb * 512;

    const float* __restrict__ Xg = g_O + (size_t)mb * NN * DI;
    const float* __restrict__ WT = WTbase + (size_t)mod * 512 * 512;

    const int tid = threadIdx.x;
    const int wid = tid >> 5, lane = tid & 31;
    const int grp = lane >> 2, l4 = lane & 3;
    const int wm = wid >> 2, wn = wid & 3;

    float c[4][4][4];
#pragma unroll
    for (int mt = 0; mt < 4; mt++)
#pragma unroll
        for (int nt = 0; nt < 4; nt++)
#pragma unroll
            for (int e = 0; e < 4; e++) c[mt][nt][e] = 0.f;

    const int rr = tid >> 3, cc = (tid & 7) << 2;

    const float* arow[4];
#pragma unroll
    for (int i = 0; i < 4; i++)
        arow[i] = Xg + (size_t)idxp[min(rowbase + rr + i * 32, gmax)] * DI;

    auto ldg_async = [&](int stage, int k0) {
        unsigned* Xst = Xs + stage * XS_W;
        unsigned* Wst = Ws + stage * WS_W;
#pragma unroll
        for (int i = 0; i < 4; i++) {
            cpa16(&Xst[(rr + i * 32) * SA + cc], arow[i] + k0 + cc);
            cpa16(&Wst[(rr + i * 32) * SBT + cc],
                  WT + (size_t)(colbase + rr + i * 32) * 512 + k0 + cc);
        }
    };

    ldg_async(0, 0);
    CP_COMMIT;

    for (int chunk = 0; chunk < 16; chunk++) {
        if (chunk < 15) {
            ldg_async((chunk + 1) & 1, (chunk + 1) * 32);
            CP_COMMIT;
            CP_WAIT1;
        } else {
            CP_WAIT0;
        }
        __syncthreads();

        const unsigned* Xst = Xs + (chunk & 1) * XS_W;
        const unsigned* Wst = Ws + (chunk & 1) * WS_W;
#pragma unroll
        for (int k8 = 0; k8 < 4; k8++) {
            unsigned a[4][4];
#pragma unroll
            for (int mt = 0; mt < 4; mt++) {
                int r0 = wm * 64 + mt * 16 + grp;
                uint2 p0 = *(const uint2*)&Xst[r0 * SA + k8 * 8 + l4 * 2];
                uint2 p1 = *(const uint2*)&Xst[(r0 + 8) * SA + k8 * 8 + l4 * 2];
                a[mt][0] = p0.x; a[mt][2] = p0.y;
                a[mt][1] = p1.x; a[mt][3] = p1.y;
            }
#pragma unroll
            for (int nt = 0; nt < 4; nt++) {
                int col = wn * 32 + nt * 8 + grp;
                uint2 bp = *(const uint2*)&Wst[col * SBT + k8 * 8 + l4 * 2];
                unsigned bb[2] = {bp.x, bp.y};
#pragma unroll
                for (int mt = 0; mt < 4; mt++) mma8(c[mt][nt], a[mt], bb);
            }
        }
        __syncthreads();
    }

    // Epilogue: scatter to original output rows (guarded)
#pragma unroll
    for (int mt = 0; mt < 4; mt++) {
        int gr0 = rowbase + wm * 64 + mt * 16 + grp;
        int gr1 = gr0 + 8;
#pragma unroll
        for (int nt = 0; nt < 4; nt++) {
            int gc = colbase + wn * 32 + nt * 8 + l4 * 2;
            if (gr0 < cnt) {
                size_t orow = (size_t)mod * 4096 + b * NN + idxp[gr0];
                *(float2*)(out + orow * 512 + gc) = make_float2(c[mt][nt][0], c[mt][nt][1]);
            }
            if (gr1 < cnt) {
                size_t orow = (size_t)mod * 4096 + b * NN + idxp[gr1];
                *(float2*)(out + orow * 512 + gc) = make_float2(c[mt][nt][2], c[mt][nt][3]);
            }
        }
    }
}

// ---------------------------------------------------------------------------
// Flash attention: 128-query tiles (halved K/V L2 traffic), 256 threads
// (8 warps x 16 rows). Fixed-max softmax, shuffle-free P->A.
// grid (4 qtiles of 128, 64 bh, 3 mod); early exit past cnt.
// ---------------------------------------------------------------------------
#define SK 72
#define SV 72
#define KS_W (64 * SK)
#define VS_W (64 * SV)
#define ATT_SMEM ((2 * KS_W + 2 * VS_W) * 4)

__global__ __launch_bounds__(256) void attn_tc() {
    extern __shared__ unsigned sh[];
    unsigned* Ks = sh;
    unsigned* Vs = sh + 2 * KS_W;

    const int mod = blockIdx.z;
    const int bh = blockIdx.y;
    const int b = bh >> 3, h = bh & 7;
    const int qt = blockIdx.x;                 // 128-row compacted q tile
    const int mb = mod * 8 + b;

    const int cnt = g_cnt[mb];
    if (qt * 128 >= cnt) return;

    const int tid = threadIdx.x;
    const int wid = tid >> 5, lane = tid & 31;
    const int grp = lane >> 2, l4 = lane & 3;

    const int r0 = wid * 16 + grp;             // within 128-row tile
    const int r1 = r0 + 8;
    const int gr0 = qt * 128 + r0, gr1 = qt * 128 + r1;
    const int gmax = cnt - 1;
    const int* idxp = g_idx + mb * 512;
    const int i0 = idxp[min(gr0, gmax)];
    const int i1 = idxp[min(gr1, gmax)];

    const float* Qg = g_Q + (((size_t)mb * HH + h) * NN) * DH;
    unsigned qa[8][4];
#pragma unroll
    for (int k8 = 0; k8 < 8; k8++) {
        float2 p0 = *(const float2*)(Qg + (size_t)i0 * 64 + k8 * 8 + l4 * 2);
        float2 p1 = *(const float2*)(Qg + (size_t)i1 * 64 + k8 * 8 + l4 * 2);
        qa[k8][0] = __float_as_uint(p0.x);
        qa[k8][2] = __float_as_uint(p0.y);
        qa[k8][1] = __float_as_uint(p1.x);
        qa[k8][3] = __float_as_uint(p1.y);
    }

    float l_0 = 0.f, l_1 = 0.f;
    float o[8][4];
#pragma unroll
    for (int nt = 0; nt < 8; nt++)
#pragma unroll
        for (int e = 0; e < 4; e++) o[nt][e] = 0.f;

    const float* Kg = g_K + (size_t)bh * N3 * DH;
    const float* VTg = g_VT + (size_t)bh * DH * N3;

    // 256 threads: K tile 64x64 = 1024 f4 chunks, V tile likewise.
    auto ldkv_async = [&](int stage, int kt) {
        unsigned* Kst = Ks + stage * KS_W;
        unsigned* Vst = Vs + stage * VS_W;
#pragma unroll
        for (int i = 0; i < 4; i++) {
            int v = tid + i * 256;
            int r = v >> 4, c4 = (v & 15) << 2;
            cpa16(&Kst[r * SK + c4], Kg + (size_t)(kt * 64 + r) * 64 + c4);
            cpa16(&Vst[r * SV + c4], VTg + (size_t)r * N3 + kt * 64 + c4);
        }
    };

    ldkv_async(0, 0);
    CP_COMMIT;

    for (int kt = 0; kt < 24; kt++) {
        if (kt < 23) {
            ldkv_async((kt + 1) & 1, kt + 1);
            CP_COMMIT;
            CP_WAIT1;
        } else {
            CP_WAIT0;
        }
        __syncthreads();

        const unsigned* Kst = Ks + (kt & 1) * KS_W;
        const unsigned* Vst = Vs + (kt & 1) * VS_W;

        // S = Q K^T
        float s[8][4];
#pragma unroll
        for (int nt = 0; nt < 8; nt++)
#pragma unroll
            for (int e = 0; e < 4; e++) s[nt][e] = 0.f;
#pragma unroll
        for (int k8 = 0; k8 < 8; k8++) {
#pragma unroll
            for (int nt = 0; nt < 8; nt++) {
                int key = nt * 8 + grp;
                uint2 bp = *(const uint2*)&Kst[key * SK + k8 * 8 + l4 * 2];
                unsigned bf[2] = {bp.x, bp.y};
                mma8(s[nt], qa[k8], bf);
            }
        }

        // Fixed-max softmax: P = exp(S - FIXMAX).
        float sum0 = 0.f, sum1 = 0.f;
#pragma unroll
        for (int nt = 0; nt < 8; nt++) {
            s[nt][0] = __expf(s[nt][0] - FIXMAX);
            s[nt][1] = __expf(s[nt][1] - FIXMAX);
            s[nt][2] = __expf(s[nt][2] - FIXMAX);
            s[nt][3] = __expf(s[nt][3] - FIXMAX);
            sum0 += s[nt][0] + s[nt][1];
            sum1 += s[nt][2] + s[nt][3];
        }
        sum0 += __shfl_xor_sync(0xffffffffu, sum0, 1);
        sum0 += __shfl_xor_sync(0xffffffffu, sum0, 2);
        sum1 += __shfl_xor_sync(0xffffffffu, sum1, 1);
        sum1 += __shfl_xor_sync(0xffffffffu, sum1, 2);
        l_0 += sum0;
        l_1 += sum1;

        // O += P @ V — S C-frag reused directly as A-frag (no shuffles).
#pragma unroll
        for (int k8 = 0; k8 < 8; k8++) {
            unsigned pa[4];
            pa[0] = f2t(s[k8][0]);
            pa[1] = f2t(s[k8][2]);
            pa[2] = f2t(s[k8][1]);
            pa[3] = f2t(s[k8][3]);
#pragma unroll
            for (int nt = 0; nt < 8; nt++) {
                int drow = nt * 8 + grp;
                uint2 bp = *(const uint2*)&Vst[drow * SV + k8 * 8 + l4 * 2];
                unsigned bf[2] = {bp.x, bp.y};
                mma8(o[nt], pa, bf);
            }
        }
        __syncthreads();
    }

    // Epilogue: normalize, tf32-round, scatter to original rows (perm-d cols)
    float linv0 = 1.f / l_0, linv1 = 1.f / l_1;
    size_t base0 = ((size_t)mb * NN + i0) * DI + h * 64;
    size_t base1 = ((size_t)mb * NN + i1) * DI + h * 64;
    const int pd0 = perm8(2 * l4);
    const int pd1 = perm8(2 * l4 + 1);
    if (gr0 < cnt) {
#pragma unroll
        for (int nt = 0; nt < 8; nt++) {
            g_O[base0 + nt * 8 + pd0] = tf32r(o[nt][0] * linv0);
            g_O[base0 + nt * 8 + pd1] = tf32r(o[nt][1] * linv0);
        }
    }
    if (gr1 < cnt) {
#pragma unroll
        for (int nt = 0; nt < 8; nt++) {
            g_O[base1 + nt * 8 + pd0] = tf32r(o[nt][2] * linv1);
            g_O[base1 + nt * 8 + pd1] = tf32r(o[nt][3] * linv1);
        }
    }
}

// ---------------------------------------------------------------------------
// Input order: 0:x0 1:m0 2:Wqkv0 3:Wout0 | 4:x1 5:m1 6:Wqkv1 7:Wout1 | 8:...
// ---------------------------------------------------------------------------
extern "C" void kernel_launch(void* const* d_in, const int* in_sizes, int n_in,
                              void* d_out, int out_size) {
    const float* x0  = (const float*)d_in[0];
    const int*   m0  = (const int*)d_in[1];
    const float* wq0 = (const float*)d_in[2];
    const float* wo0 = (const float*)d_in[3];
    const float* x1  = (const float*)d_in[4];
    const int*   m1  = (const int*)d_in[5];
    const float* wq1 = (const float*)d_in[6];
    const float* wo1 = (const float*)d_in[7];
    const float* x2  = (const float*)d_in[8];
    const int*   m2  = (const int*)d_in[9];
    const float* wq2 = (const float*)d_in[10];
    const float* wo2 = (const float*)d_in[11];
    float* out = (float*)d_out;

    static int configured = 0;
    if (!configured) {
        cudaFuncSetAttribute(gemm_qkv,
                             cudaFuncAttributeMaxDynamicSharedMemorySize, GEMM_SMEM);
        cudaFuncSetAttribute(gemm_out,
                             cudaFuncAttributeMaxDynamicSharedMemorySize, GEMM_SMEM);
        cudaFuncSetAttribute(attn_tc,
                             cudaFuncAttributeMaxDynamicSharedMemorySize, ATT_SMEM);
        configured = 1;
    }

    float *gx, *gwqt, *gwot;
    cudaGetSymbolAddress((void**)&gx, g_X);
    cudaGetSymbolAddress((void**)&gwqt, g_WqT);
    cudaGetSymbolAddress((void**)&gwot, g_WoT);

    prep_x<<<dim3(2048, 3), 256>>>(x0, x1, x2);
    transpose_w<<<dim3(48, 16, 6), dim3(32, 8)>>>(wq0, wq1, wq2, wo0, wo1, wo2);
    compact_mask<<<24, 512>>>(m0, m1, m2);
    gemm_qkv<<<dim3(12, 32, 3), 256, GEMM_SMEM>>>(gx, gwqt);
    mean_v<<<64, 128>>>();
    mvout_gemm<<<24, 512>>>();
    scatter_masked_out<<<dim3(64, 24), 512>>>(m0, m1, m2, out);
    attn_tc<<<dim3(4, 64, 3), 256, ATT_SMEM>>>();
    gemm_out<<<dim3(4, 4, 24), 256, GEMM_SMEM>>>(gwot, out);
}